// round 9
// baseline (speedup 1.0000x reference)
#include <cuda_runtime.h>
#include <cstdint>
#include <cfloat>

#define BB 8
#define NN 1024
#define KK 20
#define BN (BB*NN)
#define EPSV 1e-5f

// ---------------- scratch (device globals; no runtime allocation) ----------------
__device__ float g_pair[(size_t)BB*NN*NN];   // 32MB pairwise affinities
__device__ float g_xt[BB*128*NN];            // transposed features (B, C, N), C<=128
__device__ float g_sq[BN];
__device__ int   g_idx[BN*KK];
__device__ float g_ad[BN*512];               // [a | d] per point, width Nw (<=512)
__device__ float g_ymax[BN*256];
__device__ float g_ymin[BN*256];
__device__ float g_ps1[BN*256];              // per-(b,n) partial sum of y over k
__device__ float g_ps2[BN*256];              // per-(b,n) partial sum of y^2 over k
__device__ float g_cat[BN*512];              // concatenated block outputs (B, N, 512)
__device__ float g_wta[512*512];             // [W1 | (W2-W1)]^T : (C x Nw)
__device__ float g_cs1[16*512];
__device__ float g_cs2[16*512];
__device__ float g_stats[512*3];             // mean, scale(=g*rsqrt(v+eps)), beta
__device__ float g_bmax[BB*512];
__device__ float g_bmin[BB*512];
__device__ float g_bs1[BB*512];
__device__ float g_bs2[BB*512];
__device__ float g_feat[BB*512];

__device__ __forceinline__ const float* src_ptr(const float* ext, int coff) {
    return ext ? ext : (g_cat + coff);
}

// ---------------- fused per-stage prep: weight transpose + feature transpose + sq norms ----------------
// blocks [0,nW): g_wta (C x 2O) = [W1^T | (W2-W1)^T]
// blocks [nW,nW+nX): g_xt[b][c][n] = src[(b*N+n)*ld + c]
// blocks [nW+nX, ...): g_sq[r] = |x_r|^2
__global__ void k_prep(const float* __restrict__ w, int C, int O,
                       const float* ext, int ldx, int coff, int nW, int nX) {
    int bid = blockIdx.x;
    int tid = threadIdx.x;
    if (bid < nW) {
        int i = bid * 256 + tid;
        if (i < C * O) {
            int c = i / O, o = i % O;
            int Nw = 2 * O;
            float a = w[o * 2 * C + c];
            g_wta[c * Nw + o] = a;
            g_wta[c * Nw + O + o] = w[o * 2 * C + C + c] - a;
        }
    } else if (bid < nW + nX) {
        int i = (bid - nW) * 256 + tid;
        int n = i % NN;
        int c = (i / NN) % C;
        int b = i / (NN * C);
        const float* src = src_ptr(ext, coff);
        g_xt[(b * C + c) * NN + n] = src[(size_t)(b * NN + n) * ldx + c];
    } else {
        int r = (bid - nW - nX) * 256 + tid;
        const float* src = src_ptr(ext, coff) + (size_t)r * ldx;
        float s = 0.f;
        for (int c = 0; c < C; c++) { float v = src[c]; s += v * v; }
        g_sq[r] = s;
    }
}

// ---------------- weight transpose only (final stage) ----------------
__global__ void k_prep_w(const float* __restrict__ w, int C, int O) {
    int i = blockIdx.x * 256 + threadIdx.x;
    if (i >= C * O) return;
    int c = i / O, o = i % O;
    g_wta[c * O + o] = w[o * C + c];
}

// ---------------- pairwise affinity, 128x128 tiles, 8x8/thread, symmetric, double-buffered ----------------
// pair[b][n][m] = 2<x_n,x_m> - |x_n|^2 - |x_m|^2 ; only tn<=tm tiles computed, mirrored.
__global__ __launch_bounds__(256) void k_pair(int C) {
    __shared__ float As[2][8][132];
    __shared__ float Bs[2][8][132];
    int b = blockIdx.z;
    int t = blockIdx.x;                       // triangular tile id in [0,36)
    int tn = 0;
    while (t >= 8 - tn) { t -= 8 - tn; tn++; }
    int tm = tn + t;
    int n0 = tn * 128, m0 = tm * 128;
    const float* xt = g_xt + (size_t)b * C * NN;
    int tid = threadIdx.x;
    int tx = tid & 15, ty = tid >> 4;
    int lk = tid >> 5, ln4 = (tid & 31) * 4;

    float acc[8][8];
#pragma unroll
    for (int i = 0; i < 8; i++)
#pragma unroll
        for (int j = 0; j < 8; j++) acc[i][j] = 0.f;

    // prologue: tile c0=0
    {
        float4 va = make_float4(0.f, 0.f, 0.f, 0.f), vb = va;
        if (lk < C) {
            va = *(const float4*)&xt[lk * NN + n0 + ln4];
            vb = *(const float4*)&xt[lk * NN + m0 + ln4];
        }
        *(float4*)&As[0][lk][ln4] = va;
        *(float4*)&Bs[0][lk][ln4] = vb;
    }
    __syncthreads();

    int buf = 0;
    for (int c0 = 0; c0 < C; c0 += 8) {
        bool has = (c0 + 8) < C;           // C multiple of 8 when > 8 => unguarded loads safe
        float4 nva, nvb;
        if (has) {
            nva = *(const float4*)&xt[(c0 + 8 + lk) * NN + n0 + ln4];
            nvb = *(const float4*)&xt[(c0 + 8 + lk) * NN + m0 + ln4];
        }
#pragma unroll
        for (int k = 0; k < 8; k++) {
            float4 a0 = *(const float4*)&As[buf][k][ty * 4];
            float4 a1 = *(const float4*)&As[buf][k][64 + ty * 4];
            float4 b0 = *(const float4*)&Bs[buf][k][tx * 4];
            float4 b1 = *(const float4*)&Bs[buf][k][64 + tx * 4];
            float ar[8] = {a0.x, a0.y, a0.z, a0.w, a1.x, a1.y, a1.z, a1.w};
            float br[8] = {b0.x, b0.y, b0.z, b0.w, b1.x, b1.y, b1.z, b1.w};
#pragma unroll
            for (int i = 0; i < 8; i++)
#pragma unroll
                for (int j = 0; j < 8; j++) acc[i][j] += ar[i] * br[j];
        }
        if (has) {
            *(float4*)&As[buf ^ 1][lk][ln4] = nva;
            *(float4*)&Bs[buf ^ 1][lk][ln4] = nvb;
        }
        __syncthreads();
        buf ^= 1;
    }

    float sqn[8], sqm[8];
#pragma unroll
    for (int i = 0; i < 8; i++) {
        sqn[i] = g_sq[b * NN + n0 + (i >> 2) * 64 + ty * 4 + (i & 3)];
        sqm[i] = g_sq[b * NN + m0 + (i >> 2) * 64 + tx * 4 + (i & 3)];
    }
#pragma unroll
    for (int i = 0; i < 8; i++)
#pragma unroll
        for (int j = 0; j < 8; j++)
            acc[i][j] = 2.f * acc[i][j] - sqn[i] - sqm[j];

    float* base = g_pair + (size_t)b * NN * NN;
    // normal tile: rows n, coalesced float4
#pragma unroll
    for (int i = 0; i < 8; i++) {
        int n = n0 + (i >> 2) * 64 + ty * 4 + (i & 3);
        float* dst = base + (size_t)n * NN + m0;
        *(float4*)&dst[tx * 4]      = make_float4(acc[i][0], acc[i][1], acc[i][2], acc[i][3]);
        *(float4*)&dst[64 + tx * 4] = make_float4(acc[i][4], acc[i][5], acc[i][6], acc[i][7]);
    }
    // mirror tile (off-diagonal only): rows m, float4 along n
    if (tn != tm) {
#pragma unroll
        for (int j = 0; j < 8; j++) {
            int m = m0 + (j >> 2) * 64 + tx * 4 + (j & 3);
            float* dst = base + (size_t)m * NN + n0;
            *(float4*)&dst[ty * 4]      = make_float4(acc[0][j], acc[1][j], acc[2][j], acc[3][j]);
            *(float4*)&dst[64 + ty * 4] = make_float4(acc[4][j], acc[5][j], acc[6][j], acc[7][j]);
        }
    }
}

// ---------------- top-K: warp per row; lane-local sorted top-20, then 20 warp-argmax rounds ----------------
__global__ __launch_bounds__(256) void k_topk() {
    __shared__ float sv[8][32][21];
    __shared__ int   si[8][32][21];
    int warp = threadIdx.x >> 5, lane = threadIdx.x & 31;
    int r = blockIdx.x * 8 + warp;
    int b = r >> 10, n = r & 1023;
    const float* row = g_pair + (size_t)b * NN * NN + (size_t)n * NN;

    float* v = sv[warp][lane];
    int* ii = si[warp][lane];
#pragma unroll
    for (int t = 0; t < KK; t++) { v[t] = -FLT_MAX; ii[t] = 1 << 30; }

    for (int j = lane; j < NN; j += 32) {
        float p = row[j];
        if (p > v[KK - 1]) {                       // strict: equal keeps earlier (lower) index
            int pos = KK - 1;
            while (pos > 0 && v[pos - 1] < p) {    // strict: stable among ties
                v[pos] = v[pos - 1]; ii[pos] = ii[pos - 1]; pos--;
            }
            v[pos] = p; ii[pos] = j;
        }
    }
    __syncwarp();

    int ptr = 0;
    for (int t = 0; t < KK; t++) {
        float hv = (ptr < KK) ? v[ptr] : -FLT_MAX;
        int   hi = (ptr < KK) ? ii[ptr] : (1 << 30);
        float bv = hv; int bi = hi;
#pragma unroll
        for (int off = 16; off; off >>= 1) {
            float ov = __shfl_xor_sync(0xffffffffu, bv, off);
            int   oi = __shfl_xor_sync(0xffffffffu, bi, off);
            if (ov > bv || (ov == bv && oi < bi)) { bv = ov; bi = oi; }
        }
        if (hi == bi) ptr++;                       // winner lane (indices unique) advances
        if (lane == 0) g_idx[r * KK + t] = bi;
    }
}

// ---------------- SGEMM 128x128x8, 8x8/thread, double-buffered: g_ad = X @ g_wta ----------------
__global__ __launch_bounds__(256) void k_gemm(const float* ext, int ldx, int coff, int C, int Nw) {
    __shared__ float As[2][8][132];   // As[buf][k][m]
    __shared__ float Bs[2][8][132];   // Bs[buf][k][n]
    const float* X = src_ptr(ext, coff);
    int n0 = blockIdx.x * 128;
    int m0 = blockIdx.y * 128;
    int tid = threadIdx.x;
    int tx = tid & 15, ty = tid >> 4;
    int arow = tid >> 1, akq = (tid & 1) * 4;
    int bk = tid >> 5, bn4 = (tid & 31) * 4;

    float acc[8][8];
#pragma unroll
    for (int i = 0; i < 8; i++)
#pragma unroll
        for (int j = 0; j < 8; j++) acc[i][j] = 0.f;

    const float* Xr = X + (size_t)(m0 + arow) * ldx + akq;

    // prologue (guarded for C=3)
    {
        float4 xv = make_float4(0.f, 0.f, 0.f, 0.f);
        if (akq + 3 < C) {
            xv = *(const float4*)Xr;
        } else {
            if (akq + 0 < C) xv.x = Xr[0];
            if (akq + 1 < C) xv.y = Xr[1];
            if (akq + 2 < C) xv.z = Xr[2];
        }
        As[0][akq + 0][arow] = xv.x;
        As[0][akq + 1][arow] = xv.y;
        As[0][akq + 2][arow] = xv.z;
        As[0][akq + 3][arow] = xv.w;
        float4 wv = make_float4(0.f, 0.f, 0.f, 0.f);
        if (bk < C) wv = *(const float4*)&g_wta[(size_t)bk * Nw + n0 + bn4];
        *(float4*)&Bs[0][bk][bn4] = wv;
    }
    __syncthreads();

    int buf = 0;
    for (int c0 = 0; c0 < C; c0 += 8) {
        bool has = (c0 + 8) < C;           // C multiple of 8 when > 8 => unguarded loads safe
        float4 nxv, nwv;
        if (has) {
            nxv = *(const float4*)(Xr + c0 + 8);
            nwv = *(const float4*)&g_wta[(size_t)(c0 + 8 + bk) * Nw + n0 + bn4];
        }
#pragma unroll
        for (int k = 0; k < 8; k++) {
            float4 a0 = *(const float4*)&As[buf][k][ty * 4];
            float4 a1 = *(const float4*)&As[buf][k][64 + ty * 4];
            float4 b0 = *(const float4*)&Bs[buf][k][tx * 4];
            float4 b1 = *(const float4*)&Bs[buf][k][64 + tx * 4];
            float ar[8] = {a0.x, a0.y, a0.z, a0.w, a1.x, a1.y, a1.z, a1.w};
            float br[8] = {b0.x, b0.y, b0.z, b0.w, b1.x, b1.y, b1.z, b1.w};
#pragma unroll
            for (int i = 0; i < 8; i++)
#pragma unroll
                for (int j = 0; j < 8; j++) acc[i][j] += ar[i] * br[j];
        }
        if (has) {
            As[buf ^ 1][akq + 0][arow] = nxv.x;
            As[buf ^ 1][akq + 1][arow] = nxv.y;
            As[buf ^ 1][akq + 2][arow] = nxv.z;
            As[buf ^ 1][akq + 3][arow] = nxv.w;
            *(float4*)&Bs[buf ^ 1][bk][bn4] = nwv;
        }
        __syncthreads();
        buf ^= 1;
    }
#pragma unroll
    for (int i = 0; i < 8; i++) {
        int m = m0 + (i >> 2) * 64 + ty * 4 + (i & 3);
        float* dst = g_ad + (size_t)m * Nw + n0;
        *(float4*)&dst[tx * 4]      = make_float4(acc[i][0], acc[i][1], acc[i][2], acc[i][3]);
        *(float4*)&dst[64 + tx * 4] = make_float4(acc[i][4], acc[i][5], acc[i][6], acc[i][7]);
    }
}

// ---------------- gather + per-(b,n) max/min over k + partial channel sums ----------------
__global__ void k_gather(int O, int Ow) {
    int r = blockIdx.x;
    int b = r >> 10;
    __shared__ int sidx[KK];
    if (threadIdx.x < KK) sidx[threadIdx.x] = g_idx[r * KK + threadIdx.x];
    __syncthreads();
    int o = threadIdx.x;
    float dv = g_ad[(size_t)r * Ow + O + o];
    float ymx = -FLT_MAX, ymn = FLT_MAX, s1 = 0.f, s2 = 0.f;
#pragma unroll
    for (int k = 0; k < KK; k++) {
        float y = g_ad[(size_t)(b * NN + sidx[k]) * Ow + o] + dv;
        ymx = fmaxf(ymx, y);
        ymn = fminf(ymn, y);
        s1 += y;
        s2 += y * y;
    }
    g_ymax[(size_t)r * O + o] = ymx;
    g_ymin[(size_t)r * O + o] = ymn;
    g_ps1[(size_t)r * O + o] = s1;
    g_ps2[(size_t)r * O + o] = s2;
}

// ---------------- deterministic channel-stat reduction (2 levels) ----------------
__global__ void k_stat1(int O) {
    int ox = threadIdx.x & 31;
    int wy = threadIdx.x >> 5;
    int o = blockIdx.x * 32 + ox;
    int ci = blockIdx.y;
    const int CH = BN / 16;
    float s1 = 0.f, s2 = 0.f;
    int r0 = ci * CH;
    for (int r = r0 + wy; r < r0 + CH; r += 8) {
        s1 += g_ps1[(size_t)r * O + o];
        s2 += g_ps2[(size_t)r * O + o];
    }
    __shared__ float sh1[8][32], sh2[8][32];
    sh1[wy][ox] = s1; sh2[wy][ox] = s2;
    __syncthreads();
    if (wy == 0) {
        for (int w = 1; w < 8; w++) { s1 += sh1[w][ox]; s2 += sh2[w][ox]; }
        g_cs1[ci * O + o] = s1;
        g_cs2[ci * O + o] = s2;
    }
}

__global__ void k_stat2(int O, const float* __restrict__ g, const float* __restrict__ be, float invcnt) {
    int o = blockIdx.x * 256 + threadIdx.x;
    if (o >= O) return;
    float s1 = 0.f, s2 = 0.f;
    for (int ci = 0; ci < 16; ci++) { s1 += g_cs1[ci * O + o]; s2 += g_cs2[ci * O + o]; }
    float m = s1 * invcnt;
    float v = s2 * invcnt - m * m;
    float sc = g[o] * rsqrtf(v + EPSV);
    g_stats[o * 3 + 0] = m;
    g_stats[o * 3 + 1] = sc;
    g_stats[o * 3 + 2] = be[o];
}

// ---------------- finalize a block: pick max/min by sign(scale), BN affine, lrelu ----------------
__global__ void k_final(int O, int coff) {
    int r = blockIdx.x;
    int o = threadIdx.x;
    float m = g_stats[o * 3 + 0];
    float sc = g_stats[o * 3 + 1];
    float be = g_stats[o * 3 + 2];
    float y = (sc >= 0.f) ? g_ymax[(size_t)r * O + o] : g_ymin[(size_t)r * O + o];
    float t = (y - m) * sc + be;
    g_cat[(size_t)r * 512 + coff + o] = (t >= 0.f) ? t : 0.2f * t;
}

// ---------------- final stage: per-(b,o) max/min over N + channel sums ----------------
__global__ void k_fred() {
    int ox = threadIdx.x & 31;
    int wy = threadIdx.x >> 5;
    int o = blockIdx.x * 32 + ox;
    int b = blockIdx.y;
    float mx = -FLT_MAX, mn = FLT_MAX, s1 = 0.f, s2 = 0.f;
    for (int n = wy; n < NN; n += 8) {
        float v = g_ad[(size_t)(b * NN + n) * 512 + o];
        mx = fmaxf(mx, v);
        mn = fminf(mn, v);
        s1 += v;
        s2 += v * v;
    }
    __shared__ float smx[8][32], smn[8][32], ss1[8][32], ss2[8][32];
    smx[wy][ox] = mx; smn[wy][ox] = mn; ss1[wy][ox] = s1; ss2[wy][ox] = s2;
    __syncthreads();
    if (wy == 0) {
        for (int w = 1; w < 8; w++) {
            mx = fmaxf(mx, smx[w][ox]);
            mn = fminf(mn, smn[w][ox]);
            s1 += ss1[w][ox];
            s2 += ss2[w][ox];
        }
        g_bmax[b * 512 + o] = mx;
        g_bmin[b * 512 + o] = mn;
        g_bs1[b * 512 + o] = s1;
        g_bs2[b * 512 + o] = s2;
    }
}

__global__ void k_feat(const float* __restrict__ g5, const float* __restrict__ b5) {
    int o = blockIdx.x * 256 + threadIdx.x;
    if (o >= 512) return;
    float s1 = 0.f, s2 = 0.f;
    for (int b = 0; b < BB; b++) { s1 += g_bs1[b * 512 + o]; s2 += g_bs2[b * 512 + o]; }
    float m = s1 / 8192.f;
    float v = s2 / 8192.f - m * m;
    float sc = g5[o] * rsqrtf(v + EPSV);
    float be = b5[o];
    for (int b = 0; b < BB; b++) {
        float y = (sc >= 0.f) ? g_bmax[b * 512 + o] : g_bmin[b * 512 + o];
        float t = (y - m) * sc + be;
        g_feat[b * 512 + o] = (t >= 0.f) ? t : 0.2f * t;
    }
}

__global__ void k_out(const float* __restrict__ wemb, float* __restrict__ out) {
    int b = blockIdx.x;
    int f = threadIdx.x;  // 256
    __shared__ float fr[512];
    for (int i = threadIdx.x; i < 512; i += 256) fr[i] = g_feat[b * 512 + i];
    __syncthreads();
    float acc = 0.f;
    for (int o = 0; o < 512; o++) acc += fr[o] * wemb[f * 512 + o];
    out[b * 256 + f] = acc;
}

// ---------------- host orchestration ----------------
static void run_stage(const float* xext, int ldx, int coff, int C, int O,
                      const float* w, const float* g, const float* bb, int outcoff) {
    int Nw = 2 * O;
    int nW = (C * O + 255) / 256;
    int nX = (BB * C * NN) / 256;
    int nS = BN / 256;
    k_prep<<<nW + nX + nS, 256>>>(w, C, O, xext, ldx, coff, nW, nX);
    k_pair<<<dim3(36, 1, BB), 256>>>(C);
    k_gemm<<<dim3(Nw / 128, BN / 128), 256>>>(xext, ldx, coff, C, Nw);
    k_topk<<<BN / 8, 256>>>();
    k_gather<<<BN, O>>>(O, Nw);
    k_stat1<<<dim3(O / 32, 16), 256>>>(O);
    k_stat2<<<(O + 255) / 256, 256>>>(O, g, bb, 1.0f / (float)(BN * KK));
    k_final<<<BN, O>>>(O, outcoff);
}

extern "C" void kernel_launch(void* const* d_in, const int* in_sizes, int n_in,
                              void* d_out, int out_size) {
    const float* x    = (const float*)d_in[0];
    const float* w1   = (const float*)d_in[1];
    const float* g1   = (const float*)d_in[2];
    const float* b1   = (const float*)d_in[3];
    const float* w2   = (const float*)d_in[4];
    const float* g2   = (const float*)d_in[5];
    const float* b2   = (const float*)d_in[6];
    const float* w3   = (const float*)d_in[7];
    const float* g3   = (const float*)d_in[8];
    const float* b3   = (const float*)d_in[9];
    const float* w4   = (const float*)d_in[10];
    const float* g4   = (const float*)d_in[11];
    const float* b4   = (const float*)d_in[12];
    const float* w5   = (const float*)d_in[13];
    const float* g5   = (const float*)d_in[14];
    const float* b5   = (const float*)d_in[15];
    const float* wemb = (const float*)d_in[16];
    float* out = (float*)d_out;

    // edge blocks: input (ptr, ld, coff, C) -> output channels at outcoff in g_cat
    run_stage(x,       3,   0,   3,   64, w1, g1, b1,   0);
    run_stage(nullptr, 512, 0,   64,  64, w2, g2, b2,  64);
    run_stage(nullptr, 512, 64,  64, 128, w3, g3, b3, 128);
    run_stage(nullptr, 512, 128, 128, 256, w4, g4, b4, 256);

    // final: y5 = cat @ w5^T  (512x512), stats over (b,n), per-b max over n, lrelu, @ wemb^T
    k_prep_w<<<(512 * 512 + 255) / 256, 256>>>(w5, 512, 512);
    k_gemm<<<dim3(512 / 128, BN / 128), 256>>>(nullptr, 512, 0, 512, 512);
    k_fred<<<dim3(512 / 32, BB), 256>>>();
    k_feat<<<2, 256>>>(g5, b5);
    k_out<<<BB, 256>>>(wemb, out);
}

// round 11
// speedup vs baseline: 1.2881x; 1.2881x over previous
#include <cuda_runtime.h>
#include <cstdint>
#include <cfloat>

#define BB 8
#define NN 1024
#define KK 20
#define BN (BB*NN)
#define EPSV 1e-5f

// ---------------- scratch (device globals; no runtime allocation) ----------------
__device__ float g_pair[(size_t)BB*NN*NN];   // 32MB pairwise affinities
__device__ float g_xt[BB*128*NN];            // transposed features (B, C, N), C<=128
__device__ float g_sq[BN];
__device__ int   g_idx[BN*KK];
__device__ float g_ad[BN*512];               // [a | d] per point, width Nw (<=512)
__device__ float g_ymax[BN*256];
__device__ float g_ymin[BN*256];
__device__ float g_ps1[BN*256];              // per-(b,n) partial sum of y over k
__device__ float g_ps2[BN*256];              // per-(b,n) partial sum of y^2 over k
__device__ float g_cat[BN*512];              // concatenated block outputs (B, N, 512)
__device__ float g_wta[512*512];             // [W1 | (W2-W1)]^T : (C x Nw)
__device__ float g_cs1[16*512];
__device__ float g_cs2[16*512];
__device__ float g_stats[512*3];             // mean, scale(=g*rsqrt(v+eps)), beta
__device__ float g_bmax[BB*512];
__device__ float g_bmin[BB*512];
__device__ float g_bs1[BB*512];
__device__ float g_bs2[BB*512];
__device__ float g_feat[BB*512];

__device__ __forceinline__ const float* src_ptr(const float* ext, int coff) {
    return ext ? ext : (g_cat + coff);
}

// ---------------- fused per-stage prep: weight transpose + feature transpose + sq norms ----------------
__global__ void k_prep(const float* __restrict__ w, int C, int O,
                       const float* ext, int ldx, int coff, int nW, int nX) {
    int bid = blockIdx.x;
    int tid = threadIdx.x;
    if (bid < nW) {
        int i = bid * 256 + tid;
        if (i < C * O) {
            int c = i / O, o = i % O;
            int Nw = 2 * O;
            float a = w[o * 2 * C + c];
            g_wta[c * Nw + o] = a;
            g_wta[c * Nw + O + o] = w[o * 2 * C + C + c] - a;
        }
    } else if (bid < nW + nX) {
        int i = (bid - nW) * 256 + tid;
        int n = i % NN;
        int c = (i / NN) % C;
        int b = i / (NN * C);
        const float* src = src_ptr(ext, coff);
        g_xt[(b * C + c) * NN + n] = src[(size_t)(b * NN + n) * ldx + c];
    } else {
        int r = (bid - nW - nX) * 256 + tid;
        const float* src = src_ptr(ext, coff) + (size_t)r * ldx;
        float s = 0.f;
        for (int c = 0; c < C; c++) { float v = src[c]; s += v * v; }
        g_sq[r] = s;
    }
}

// ---------------- weight transpose only (final stage) ----------------
__global__ void k_prep_w(const float* __restrict__ w, int C, int O) {
    int i = blockIdx.x * 256 + threadIdx.x;
    if (i >= C * O) return;
    int c = i / O, o = i % O;
    g_wta[c * O + o] = w[o * C + c];
}

// ---------------- pairwise affinity, 128x128 tiles, 8x8/thread, symmetric, double-buffered ----------------
__global__ __launch_bounds__(256) void k_pair(int C) {
    __shared__ float As[2][8][132];
    __shared__ float Bs[2][8][132];
    int b = blockIdx.z;
    int t = blockIdx.x;                       // triangular tile id in [0,36)
    int tn = 0;
    while (t >= 8 - tn) { t -= 8 - tn; tn++; }
    int tm = tn + t;
    int n0 = tn * 128, m0 = tm * 128;
    const float* xt = g_xt + (size_t)b * C * NN;
    int tid = threadIdx.x;
    int tx = tid & 15, ty = tid >> 4;
    int lk = tid >> 5, ln4 = (tid & 31) * 4;

    float acc[8][8];
#pragma unroll
    for (int i = 0; i < 8; i++)
#pragma unroll
        for (int j = 0; j < 8; j++) acc[i][j] = 0.f;

    {
        float4 va = make_float4(0.f, 0.f, 0.f, 0.f), vb = va;
        if (lk < C) {
            va = *(const float4*)&xt[lk * NN + n0 + ln4];
            vb = *(const float4*)&xt[lk * NN + m0 + ln4];
        }
        *(float4*)&As[0][lk][ln4] = va;
        *(float4*)&Bs[0][lk][ln4] = vb;
    }
    __syncthreads();

    int buf = 0;
    for (int c0 = 0; c0 < C; c0 += 8) {
        bool has = (c0 + 8) < C;
        float4 nva, nvb;
        if (has) {
            nva = *(const float4*)&xt[(c0 + 8 + lk) * NN + n0 + ln4];
            nvb = *(const float4*)&xt[(c0 + 8 + lk) * NN + m0 + ln4];
        }
#pragma unroll
        for (int k = 0; k < 8; k++) {
            float4 a0 = *(const float4*)&As[buf][k][ty * 4];
            float4 a1 = *(const float4*)&As[buf][k][64 + ty * 4];
            float4 b0 = *(const float4*)&Bs[buf][k][tx * 4];
            float4 b1 = *(const float4*)&Bs[buf][k][64 + tx * 4];
            float ar[8] = {a0.x, a0.y, a0.z, a0.w, a1.x, a1.y, a1.z, a1.w};
            float br[8] = {b0.x, b0.y, b0.z, b0.w, b1.x, b1.y, b1.z, b1.w};
#pragma unroll
            for (int i = 0; i < 8; i++)
#pragma unroll
                for (int j = 0; j < 8; j++) acc[i][j] += ar[i] * br[j];
        }
        if (has) {
            *(float4*)&As[buf ^ 1][lk][ln4] = nva;
            *(float4*)&Bs[buf ^ 1][lk][ln4] = nvb;
        }
        __syncthreads();
        buf ^= 1;
    }

    float sqn[8], sqm[8];
#pragma unroll
    for (int i = 0; i < 8; i++) {
        sqn[i] = g_sq[b * NN + n0 + (i >> 2) * 64 + ty * 4 + (i & 3)];
        sqm[i] = g_sq[b * NN + m0 + (i >> 2) * 64 + tx * 4 + (i & 3)];
    }
#pragma unroll
    for (int i = 0; i < 8; i++)
#pragma unroll
        for (int j = 0; j < 8; j++)
            acc[i][j] = 2.f * acc[i][j] - sqn[i] - sqm[j];

    float* base = g_pair + (size_t)b * NN * NN;
#pragma unroll
    for (int i = 0; i < 8; i++) {
        int n = n0 + (i >> 2) * 64 + ty * 4 + (i & 3);
        float* dst = base + (size_t)n * NN + m0;
        *(float4*)&dst[tx * 4]      = make_float4(acc[i][0], acc[i][1], acc[i][2], acc[i][3]);
        *(float4*)&dst[64 + tx * 4] = make_float4(acc[i][4], acc[i][5], acc[i][6], acc[i][7]);
    }
    if (tn != tm) {
#pragma unroll
        for (int j = 0; j < 8; j++) {
            int m = m0 + (j >> 2) * 64 + tx * 4 + (j & 3);
            float* dst = base + (size_t)m * NN + n0;
            *(float4*)&dst[ty * 4]      = make_float4(acc[0][j], acc[1][j], acc[2][j], acc[3][j]);
            *(float4*)&dst[64 + ty * 4] = make_float4(acc[4][j], acc[5][j], acc[6][j], acc[7][j]);
        }
    }
}

// ---------------- top-K: warp per row, register-resident tournament select ----------------
// Each lane holds 32 values in registers; 20 rounds of warp argmax on (value, index);
// winner lane clears its register (predicated, unrolled) and recomputes its local max.
// Tie-break: lower global index wins at equal value (matches jax.lax.top_k set).
__global__ __launch_bounds__(256) void k_topk() {
    int warp = threadIdx.x >> 5, lane = threadIdx.x & 31;
    int r = blockIdx.x * 8 + warp;
    int b = r >> 10, n = r & 1023;
    const float4* row4 = (const float4*)(g_pair + (size_t)b * NN * NN + (size_t)n * NN);

    // load: reg i = q*4+e holds row[q*128 + lane*4 + e]; gidx monotonic in i
    float v[32];
#pragma unroll
    for (int q = 0; q < 8; q++) {
        float4 t4 = row4[q * 32 + lane];
        v[q * 4 + 0] = t4.x;
        v[q * 4 + 1] = t4.y;
        v[q * 4 + 2] = t4.z;
        v[q * 4 + 3] = t4.w;
    }

    // lane-local argmax (strict > keeps lowest local i => lowest global idx)
    float bm = v[0];
    int bi = 0;
#pragma unroll
    for (int i = 1; i < 32; i++) {
        bool p = v[i] > bm;
        bm = p ? v[i] : bm;
        bi = p ? i : bi;
    }

    for (int t = 0; t < KK; t++) {
        int gidx = (bi >> 2) * 128 + lane * 4 + (bi & 3);
        float wv = bm;
        int wi = gidx;
#pragma unroll
        for (int off = 16; off; off >>= 1) {
            float ov = __shfl_xor_sync(0xffffffffu, wv, off);
            int   oi = __shfl_xor_sync(0xffffffffu, wi, off);
            if (ov > wv || (ov == wv && oi < wi)) { wv = ov; wi = oi; }
        }
        if (lane == 0) g_idx[r * KK + t] = wi;
        // winner lane removes its element and recomputes local max
        if (wi == gidx) {
#pragma unroll
            for (int i = 0; i < 32; i++) v[i] = (i == bi) ? -FLT_MAX : v[i];
            bm = v[0];
            bi = 0;
#pragma unroll
            for (int i = 1; i < 32; i++) {
                bool p = v[i] > bm;
                bm = p ? v[i] : bm;
                bi = p ? i : bi;
            }
        }
    }
}

// ---------------- SGEMM 128x128x8, 8x8/thread, double-buffered: g_ad = X @ g_wta ----------------
__global__ __launch_bounds__(256) void k_gemm(const float* ext, int ldx, int coff, int C, int Nw) {
    __shared__ float As[2][8][132];   // As[buf][k][m]
    __shared__ float Bs[2][8][132];   // Bs[buf][k][n]
    const float* X = src_ptr(ext, coff);
    int n0 = blockIdx.x * 128;
    int m0 = blockIdx.y * 128;
    int tid = threadIdx.x;
    int tx = tid & 15, ty = tid >> 4;
    int arow = tid >> 1, akq = (tid & 1) * 4;
    int bk = tid >> 5, bn4 = (tid & 31) * 4;

    float acc[8][8];
#pragma unroll
    for (int i = 0; i < 8; i++)
#pragma unroll
        for (int j = 0; j < 8; j++) acc[i][j] = 0.f;

    const float* Xr = X + (size_t)(m0 + arow) * ldx + akq;

    {
        float4 xv = make_float4(0.f, 0.f, 0.f, 0.f);
        if (akq + 3 < C) {
            xv = *(const float4*)Xr;
        } else {
            if (akq + 0 < C) xv.x = Xr[0];
            if (akq + 1 < C) xv.y = Xr[1];
            if (akq + 2 < C) xv.z = Xr[2];
        }
        As[0][akq + 0][arow] = xv.x;
        As[0][akq + 1][arow] = xv.y;
        As[0][akq + 2][arow] = xv.z;
        As[0][akq + 3][arow] = xv.w;
        float4 wv = make_float4(0.f, 0.f, 0.f, 0.f);
        if (bk < C) wv = *(const float4*)&g_wta[(size_t)bk * Nw + n0 + bn4];
        *(float4*)&Bs[0][bk][bn4] = wv;
    }
    __syncthreads();

    int buf = 0;
    for (int c0 = 0; c0 < C; c0 += 8) {
        bool has = (c0 + 8) < C;
        float4 nxv, nwv;
        if (has) {
            nxv = *(const float4*)(Xr + c0 + 8);
            nwv = *(const float4*)&g_wta[(size_t)(c0 + 8 + bk) * Nw + n0 + bn4];
        }
#pragma unroll
        for (int k = 0; k < 8; k++) {
            float4 a0 = *(const float4*)&As[buf][k][ty * 4];
            float4 a1 = *(const float4*)&As[buf][k][64 + ty * 4];
            float4 b0 = *(const float4*)&Bs[buf][k][tx * 4];
            float4 b1 = *(const float4*)&Bs[buf][k][64 + tx * 4];
            float ar[8] = {a0.x, a0.y, a0.z, a0.w, a1.x, a1.y, a1.z, a1.w};
            float br[8] = {b0.x, b0.y, b0.z, b0.w, b1.x, b1.y, b1.z, b1.w};
#pragma unroll
            for (int i = 0; i < 8; i++)
#pragma unroll
                for (int j = 0; j < 8; j++) acc[i][j] += ar[i] * br[j];
        }
        if (has) {
            As[buf ^ 1][akq + 0][arow] = nxv.x;
            As[buf ^ 1][akq + 1][arow] = nxv.y;
            As[buf ^ 1][akq + 2][arow] = nxv.z;
            As[buf ^ 1][akq + 3][arow] = nxv.w;
            *(float4*)&Bs[buf ^ 1][bk][bn4] = nwv;
        }
        __syncthreads();
        buf ^= 1;
    }
#pragma unroll
    for (int i = 0; i < 8; i++) {
        int m = m0 + (i >> 2) * 64 + ty * 4 + (i & 3);
        float* dst = g_ad + (size_t)m * Nw + n0;
        *(float4*)&dst[tx * 4]      = make_float4(acc[i][0], acc[i][1], acc[i][2], acc[i][3]);
        *(float4*)&dst[64 + tx * 4] = make_float4(acc[i][4], acc[i][5], acc[i][6], acc[i][7]);
    }
}

// ---------------- gather + per-(b,n) max/min over k + partial channel sums ----------------
__global__ void k_gather(int O, int Ow) {
    int r = blockIdx.x;
    int b = r >> 10;
    __shared__ int sidx[KK];
    if (threadIdx.x < KK) sidx[threadIdx.x] = g_idx[r * KK + threadIdx.x];
    __syncthreads();
    int o = threadIdx.x;
    float dv = g_ad[(size_t)r * Ow + O + o];
    float ymx = -FLT_MAX, ymn = FLT_MAX, s1 = 0.f, s2 = 0.f;
#pragma unroll
    for (int k = 0; k < KK; k++) {
        float y = g_ad[(size_t)(b * NN + sidx[k]) * Ow + o] + dv;
        ymx = fmaxf(ymx, y);
        ymn = fminf(ymn, y);
        s1 += y;
        s2 += y * y;
    }
    g_ymax[(size_t)r * O + o] = ymx;
    g_ymin[(size_t)r * O + o] = ymn;
    g_ps1[(size_t)r * O + o] = s1;
    g_ps2[(size_t)r * O + o] = s2;
}

// ---------------- deterministic channel-stat reduction (2 levels) ----------------
__global__ void k_stat1(int O) {
    int ox = threadIdx.x & 31;
    int wy = threadIdx.x >> 5;
    int o = blockIdx.x * 32 + ox;
    int ci = blockIdx.y;
    const int CH = BN / 16;
    float s1 = 0.f, s2 = 0.f;
    int r0 = ci * CH;
    for (int r = r0 + wy; r < r0 + CH; r += 8) {
        s1 += g_ps1[(size_t)r * O + o];
        s2 += g_ps2[(size_t)r * O + o];
    }
    __shared__ float sh1[8][32], sh2[8][32];
    sh1[wy][ox] = s1; sh2[wy][ox] = s2;
    __syncthreads();
    if (wy == 0) {
        for (int w = 1; w < 8; w++) { s1 += sh1[w][ox]; s2 += sh2[w][ox]; }
        g_cs1[ci * O + o] = s1;
        g_cs2[ci * O + o] = s2;
    }
}

__global__ void k_stat2(int O, const float* __restrict__ g, const float* __restrict__ be, float invcnt) {
    int o = blockIdx.x * 256 + threadIdx.x;
    if (o >= O) return;
    float s1 = 0.f, s2 = 0.f;
    for (int ci = 0; ci < 16; ci++) { s1 += g_cs1[ci * O + o]; s2 += g_cs2[ci * O + o]; }
    float m = s1 * invcnt;
    float v = s2 * invcnt - m * m;
    float sc = g[o] * rsqrtf(v + EPSV);
    g_stats[o * 3 + 0] = m;
    g_stats[o * 3 + 1] = sc;
    g_stats[o * 3 + 2] = be[o];
}

// ---------------- finalize a block: pick max/min by sign(scale), BN affine, lrelu ----------------
__global__ void k_final(int O, int coff) {
    int r = blockIdx.x;
    int o = threadIdx.x;
    float m = g_stats[o * 3 + 0];
    float sc = g_stats[o * 3 + 1];
    float be = g_stats[o * 3 + 2];
    float y = (sc >= 0.f) ? g_ymax[(size_t)r * O + o] : g_ymin[(size_t)r * O + o];
    float t = (y - m) * sc + be;
    g_cat[(size_t)r * 512 + coff + o] = (t >= 0.f) ? t : 0.2f * t;
}

// ---------------- final stage: per-(b,o) max/min over N + channel sums ----------------
__global__ void k_fred() {
    int ox = threadIdx.x & 31;
    int wy = threadIdx.x >> 5;
    int o = blockIdx.x * 32 + ox;
    int b = blockIdx.y;
    float mx = -FLT_MAX, mn = FLT_MAX, s1 = 0.f, s2 = 0.f;
    for (int n = wy; n < NN; n += 8) {
        float v = g_ad[(size_t)(b * NN + n) * 512 + o];
        mx = fmaxf(mx, v);
        mn = fminf(mn, v);
        s1 += v;
        s2 += v * v;
    }
    __shared__ float smx[8][32], smn[8][32], ss1[8][32], ss2[8][32];
    smx[wy][ox] = mx; smn[wy][ox] = mn; ss1[wy][ox] = s1; ss2[wy][ox] = s2;
    __syncthreads();
    if (wy == 0) {
        for (int w = 1; w < 8; w++) {
            mx = fmaxf(mx, smx[w][ox]);
            mn = fminf(mn, smn[w][ox]);
            s1 += ss1[w][ox];
            s2 += ss2[w][ox];
        }
        g_bmax[b * 512 + o] = mx;
        g_bmin[b * 512 + o] = mn;
        g_bs1[b * 512 + o] = s1;
        g_bs2[b * 512 + o] = s2;
    }
}

__global__ void k_feat(const float* __restrict__ g5, const float* __restrict__ b5) {
    int o = blockIdx.x * 256 + threadIdx.x;
    if (o >= 512) return;
    float s1 = 0.f, s2 = 0.f;
    for (int b = 0; b < BB; b++) { s1 += g_bs1[b * 512 + o]; s2 += g_bs2[b * 512 + o]; }
    float m = s1 / 8192.f;
    float v = s2 / 8192.f - m * m;
    float sc = g5[o] * rsqrtf(v + EPSV);
    float be = b5[o];
    for (int b = 0; b < BB; b++) {
        float y = (sc >= 0.f) ? g_bmax[b * 512 + o] : g_bmin[b * 512 + o];
        float t = (y - m) * sc + be;
        g_feat[b * 512 + o] = (t >= 0.f) ? t : 0.2f * t;
    }
}

__global__ void k_out(const float* __restrict__ wemb, float* __restrict__ out) {
    int b = blockIdx.x;
    int f = threadIdx.x;  // 256
    __shared__ float fr[512];
    for (int i = threadIdx.x; i < 512; i += 256) fr[i] = g_feat[b * 512 + i];
    __syncthreads();
    float acc = 0.f;
    for (int o = 0; o < 512; o++) acc += fr[o] * wemb[f * 512 + o];
    out[b * 256 + f] = acc;
}

// ---------------- host orchestration ----------------
static void run_stage(const float* xext, int ldx, int coff, int C, int O,
                      const float* w, const float* g, const float* bb, int outcoff) {
    int Nw = 2 * O;
    int nW = (C * O + 255) / 256;
    int nX = (BB * C * NN) / 256;
    int nS = BN / 256;
    k_prep<<<nW + nX + nS, 256>>>(w, C, O, xext, ldx, coff, nW, nX);
    k_pair<<<dim3(36, 1, BB), 256>>>(C);
    k_gemm<<<dim3(Nw / 128, BN / 128), 256>>>(xext, ldx, coff, C, Nw);
    k_topk<<<BN / 8, 256>>>();
    k_gather<<<BN, O>>>(O, Nw);
    k_stat1<<<dim3(O / 32, 16), 256>>>(O);
    k_stat2<<<(O + 255) / 256, 256>>>(O, g, bb, 1.0f / (float)(BN * KK));
    k_final<<<BN, O>>>(O, outcoff);
}

extern "C" void kernel_launch(void* const* d_in, const int* in_sizes, int n_in,
                              void* d_out, int out_size) {
    const float* x    = (const float*)d_in[0];
    const float* w1   = (const float*)d_in[1];
    const float* g1   = (const float*)d_in[2];
    const float* b1   = (const float*)d_in[3];
    const float* w2   = (const float*)d_in[4];
    const float* g2   = (const float*)d_in[5];
    const float* b2   = (const float*)d_in[6];
    const float* w3   = (const float*)d_in[7];
    const float* g3   = (const float*)d_in[8];
    const float* b3   = (const float*)d_in[9];
    const float* w4   = (const float*)d_in[10];
    const float* g4   = (const float*)d_in[11];
    const float* b4   = (const float*)d_in[12];
    const float* w5   = (const float*)d_in[13];
    const float* g5   = (const float*)d_in[14];
    const float* b5   = (const float*)d_in[15];
    const float* wemb = (const float*)d_in[16];
    float* out = (float*)d_out;

    // edge blocks: input (ptr, ld, coff, C) -> output channels at outcoff in g_cat
    run_stage(x,       3,   0,   3,   64, w1, g1, b1,   0);
    run_stage(nullptr, 512, 0,   64,  64, w2, g2, b2,  64);
    run_stage(nullptr, 512, 64,  64, 128, w3, g3, b3, 128);
    run_stage(nullptr, 512, 128, 128, 256, w4, g4, b4, 256);

    // final: y5 = cat @ w5^T  (512x512), stats over (b,n), per-b max over n, lrelu, @ wemb^T
    k_prep_w<<<(512 * 512 + 255) / 256, 256>>>(w5, 512, 512);
    k_gemm<<<dim3(512 / 128, BN / 128), 256>>>(nullptr, 512, 0, 512, 512);
    k_fred<<<dim3(512 / 32, BB), 256>>>();
    k_feat<<<2, 256>>>(g5, b5);
    k_out<<<BB, 256>>>(wemb, out);
}

// round 13
// speedup vs baseline: 1.4646x; 1.1370x over previous
#include <cuda_runtime.h>
#include <cstdint>
#include <cfloat>

#define BB 8
#define NN 1024
#define KK 20
#define BN (BB*NN)
#define EPSV 1e-5f

typedef unsigned long long ull;

__device__ __forceinline__ void unpack2(ull v, float& lo, float& hi) {
    asm("mov.b64 {%0,%1}, %2;" : "=f"(lo), "=f"(hi) : "l"(v));
}
__device__ __forceinline__ ull ffma2(ull a, ull b, ull c) {
    ull d; asm("fma.rn.f32x2 %0, %1, %2, %3;" : "=l"(d) : "l"(a), "l"(b), "l"(c)); return d;
}

// ---------------- scratch (device globals; no runtime allocation) ----------------
__device__ float g_pair[(size_t)BB*NN*NN];   // 32MB pairwise affinities
__device__ float g_xt[BB*128*NN];            // transposed features (B, C, N), C<=128
__device__ float g_sq[BN];
__device__ int   g_idx[BN*KK];
__device__ float g_ad[BN*512];               // [a | d] per point, width Nw (<=512)
__device__ float g_ymax[BN*256];
__device__ float g_ymin[BN*256];
__device__ float g_ps1[BN*256];              // per-(b,n) partial sum of y over k
__device__ float g_ps2[BN*256];              // per-(b,n) partial sum of y^2 over k
__device__ float g_cat[BN*512];              // concatenated block outputs (B, N, 512)
__device__ float g_wta[512*512];             // [W1 | (W2-W1)]^T : (C x Nw)
__device__ float g_cs1[16*512];
__device__ float g_cs2[16*512];
__device__ float g_stats[512*3];             // mean, scale(=g*rsqrt(v+eps)), beta
__device__ float g_bmax[BB*512];
__device__ float g_bmin[BB*512];
__device__ float g_bs1[BB*512];
__device__ float g_bs2[BB*512];
__device__ float g_feat[BB*512];

__device__ __forceinline__ const float* src_ptr(const float* ext, int coff) {
    return ext ? ext : (g_cat + coff);
}

// ---------------- fused per-stage prep: weight transpose + feature transpose + sq norms ----------------
__global__ void k_prep(const float* __restrict__ w, int C, int O,
                       const float* ext, int ldx, int coff, int nW, int nX) {
    int bid = blockIdx.x;
    int tid = threadIdx.x;
    if (bid < nW) {
        int i = bid * 256 + tid;
        if (i < C * O) {
            int c = i / O, o = i % O;
            int Nw = 2 * O;
            float a = w[o * 2 * C + c];
            g_wta[c * Nw + o] = a;
            g_wta[c * Nw + O + o] = w[o * 2 * C + C + c] - a;
        }
    } else if (bid < nW + nX) {
        int i = (bid - nW) * 256 + tid;
        int n = i % NN;
        int c = (i / NN) % C;
        int b = i / (NN * C);
        const float* src = src_ptr(ext, coff);
        g_xt[(b * C + c) * NN + n] = src[(size_t)(b * NN + n) * ldx + c];
    } else {
        int r = (bid - nW - nX) * 256 + tid;
        const float* src = src_ptr(ext, coff) + (size_t)r * ldx;
        float s = 0.f;
        for (int c = 0; c < C; c++) { float v = src[c]; s += v * v; }
        g_sq[r] = s;
    }
}

// ---------------- weight transpose only (final stage) ----------------
__global__ void k_prep_w(const float* __restrict__ w, int C, int O) {
    int i = blockIdx.x * 256 + threadIdx.x;
    if (i >= C * O) return;
    int c = i / O, o = i % O;
    g_wta[c * O + o] = w[o * C + c];
}

// ---------------- pairwise affinity, 128x128 tiles, 8x8/thread, symmetric, f32x2 ----------------
// A-side (n rows) duplicated in smem so LDS yields (a,a) pairs directly.
__global__ __launch_bounds__(256) void k_pair(int C) {
    __shared__ __align__(16) float As2[2][8][264];  // duplicated n-side
    __shared__ __align__(16) float Bs[2][8][132];
    int b = blockIdx.z;
    int t = blockIdx.x;                       // triangular tile id in [0,36)
    int tn = 0;
    while (t >= 8 - tn) { t -= 8 - tn; tn++; }
    int tm = tn + t;
    int n0 = tn * 128, m0 = tm * 128;
    const float* xt = g_xt + (size_t)b * C * NN;
    int tid = threadIdx.x;
    int tx = tid & 15, ty = tid >> 4;
    int lk = tid >> 5, ln = tid & 31;

    ull acc[8][4];
#pragma unroll
    for (int i = 0; i < 8; i++)
#pragma unroll
        for (int j = 0; j < 4; j++) acc[i][j] = 0ull;

    {
        float4 va = make_float4(0.f, 0.f, 0.f, 0.f), vb = va;
        if (lk < C) {
            va = *(const float4*)&xt[lk * NN + n0 + ln * 4];
            vb = *(const float4*)&xt[lk * NN + m0 + ln * 4];
        }
        *(float4*)&As2[0][lk][ln * 8]     = make_float4(va.x, va.x, va.y, va.y);
        *(float4*)&As2[0][lk][ln * 8 + 4] = make_float4(va.z, va.z, va.w, va.w);
        *(float4*)&Bs[0][lk][ln * 4] = vb;
    }
    __syncthreads();

    int buf = 0;
    for (int c0 = 0; c0 < C; c0 += 8) {
        bool has = (c0 + 8) < C;
        float4 nva, nvb;
        if (has) {
            nva = *(const float4*)&xt[(c0 + 8 + lk) * NN + n0 + ln * 4];
            nvb = *(const float4*)&xt[(c0 + 8 + lk) * NN + m0 + ln * 4];
        }
#pragma unroll
        for (int k = 0; k < 8; k++) {
            ulonglong2 a01 = *(const ulonglong2*)&As2[buf][k][ty * 8];
            ulonglong2 a23 = *(const ulonglong2*)&As2[buf][k][ty * 8 + 4];
            ulonglong2 a45 = *(const ulonglong2*)&As2[buf][k][128 + ty * 8];
            ulonglong2 a67 = *(const ulonglong2*)&As2[buf][k][128 + ty * 8 + 4];
            ulonglong2 b01 = *(const ulonglong2*)&Bs[buf][k][tx * 4];
            ulonglong2 b23 = *(const ulonglong2*)&Bs[buf][k][64 + tx * 4];
            ull ar[8] = {a01.x, a01.y, a23.x, a23.y, a45.x, a45.y, a67.x, a67.y};
            ull br[4] = {b01.x, b01.y, b23.x, b23.y};
#pragma unroll
            for (int i = 0; i < 8; i++)
#pragma unroll
                for (int j = 0; j < 4; j++) acc[i][j] = ffma2(ar[i], br[j], acc[i][j]);
        }
        if (has) {
            *(float4*)&As2[buf ^ 1][lk][ln * 8]     = make_float4(nva.x, nva.x, nva.y, nva.y);
            *(float4*)&As2[buf ^ 1][lk][ln * 8 + 4] = make_float4(nva.z, nva.z, nva.w, nva.w);
            *(float4*)&Bs[buf ^ 1][lk][ln * 4] = nvb;
        }
        __syncthreads();
        buf ^= 1;
    }

    float sqn[8], sqm[8];
#pragma unroll
    for (int i = 0; i < 8; i++) {
        sqn[i] = g_sq[b * NN + n0 + (i >> 2) * 64 + ty * 4 + (i & 3)];
        sqm[i] = g_sq[b * NN + m0 + (i >> 2) * 64 + tx * 4 + (i & 3)];
    }
    float vals[8][8];
#pragma unroll
    for (int i = 0; i < 8; i++) {
#pragma unroll
        for (int j = 0; j < 4; j++)
            unpack2(acc[i][j], vals[i][j * 2], vals[i][j * 2 + 1]);
#pragma unroll
        for (int c = 0; c < 8; c++)
            vals[i][c] = 2.f * vals[i][c] - sqn[i] - sqm[c];
    }

    float* base = g_pair + (size_t)b * NN * NN;
#pragma unroll
    for (int i = 0; i < 8; i++) {
        int n = n0 + (i >> 2) * 64 + ty * 4 + (i & 3);
        float* dst = base + (size_t)n * NN + m0;
        *(float4*)&dst[tx * 4]      = make_float4(vals[i][0], vals[i][1], vals[i][2], vals[i][3]);
        *(float4*)&dst[64 + tx * 4] = make_float4(vals[i][4], vals[i][5], vals[i][6], vals[i][7]);
    }
    if (tn != tm) {
#pragma unroll
        for (int j = 0; j < 8; j++) {
            int m = m0 + (j >> 2) * 64 + tx * 4 + (j & 3);
            float* dst = base + (size_t)m * NN + n0;
            *(float4*)&dst[ty * 4]      = make_float4(vals[0][j], vals[1][j], vals[2][j], vals[3][j]);
            *(float4*)&dst[64 + ty * 4] = make_float4(vals[4][j], vals[5][j], vals[6][j], vals[7][j]);
        }
    }
}

// ---------------- top-K: warp per row, register tournament with group-cached argmax ----------------
// 4 groups of 8 regs per lane; winner-lane recompute touches one group only.
// Tie-break: lower global index at equal value (matches jax.lax.top_k set).
__global__ __launch_bounds__(256) void k_topk() {
    int warp = threadIdx.x >> 5, lane = threadIdx.x & 31;
    int r = blockIdx.x * 8 + warp;
    int b = r >> 10, n = r & 1023;
    const float4* row4 = (const float4*)(g_pair + (size_t)b * NN * NN + (size_t)n * NN);

    float v[32];
#pragma unroll
    for (int q = 0; q < 8; q++) {
        float4 t4 = row4[q * 32 + lane];
        v[q * 4 + 0] = t4.x;
        v[q * 4 + 1] = t4.y;
        v[q * 4 + 2] = t4.z;
        v[q * 4 + 3] = t4.w;
    }

    // group (max, argmax); strict > keeps lowest local index => lowest global idx
    float gm[4]; int gi[4];
#pragma unroll
    for (int g = 0; g < 4; g++) {
        float m = v[g * 8]; int ix = g * 8;
#pragma unroll
        for (int e = 1; e < 8; e++) {
            bool p = v[g * 8 + e] > m;
            m = p ? v[g * 8 + e] : m;
            ix = p ? g * 8 + e : ix;
        }
        gm[g] = m; gi[g] = ix;
    }
    float bm = gm[0]; int bi = gi[0];
#pragma unroll
    for (int g = 1; g < 4; g++) {
        bool p = gm[g] > bm;
        bm = p ? gm[g] : bm;
        bi = p ? gi[g] : bi;
    }

    for (int t = 0; t < KK; t++) {
        int gidx = (bi >> 2) * 128 + lane * 4 + (bi & 3);
        float wv = bm;
        int wi = gidx;
#pragma unroll
        for (int off = 16; off; off >>= 1) {
            float ov = __shfl_xor_sync(0xffffffffu, wv, off);
            int   oi = __shfl_xor_sync(0xffffffffu, wi, off);
            if (ov > wv || (ov == wv && oi < wi)) { wv = ov; wi = oi; }
        }
        if (lane == 0) g_idx[r * KK + t] = wi;
        if (wi == gidx) {                    // this lane won (gidx unique across lanes)
            int g = bi >> 3;
#pragma unroll
            for (int gg = 0; gg < 4; gg++) {
                if (g == gg) {
#pragma unroll
                    for (int e = 0; e < 8; e++)
                        v[gg * 8 + e] = (gg * 8 + e == bi) ? -FLT_MAX : v[gg * 8 + e];
                    float m = v[gg * 8]; int ix = gg * 8;
#pragma unroll
                    for (int e = 1; e < 8; e++) {
                        bool p = v[gg * 8 + e] > m;
                        m = p ? v[gg * 8 + e] : m;
                        ix = p ? gg * 8 + e : ix;
                    }
                    gm[gg] = m; gi[gg] = ix;
                }
            }
            bm = gm[0]; bi = gi[0];
#pragma unroll
            for (int g2 = 1; g2 < 4; g2++) {
                bool p = gm[g2] > bm;
                bm = p ? gm[g2] : bm;
                bi = p ? gi[g2] : bi;
            }
        }
    }
}

// ---------------- SGEMM 128x128x8, 8x8/thread, double-buffered, f32x2: g_ad = X @ g_wta ----------------
__global__ __launch_bounds__(256) void k_gemm(const float* ext, int ldx, int coff, int C, int Nw) {
    __shared__ __align__(16) float As2[2][8][264];  // duplicated A: As2[k][2m+{0,1}] = A[m]
    __shared__ __align__(16) float Bs[2][8][132];   // Bs[k][n]
    const float* X = src_ptr(ext, coff);
    int n0 = blockIdx.x * 128;
    int m0 = blockIdx.y * 128;
    int tid = threadIdx.x;
    int tx = tid & 15, ty = tid >> 4;
    int arow = tid >> 1, akq = (tid & 1) * 4;
    int bk = tid >> 5, bn4 = (tid & 31) * 4;

    ull acc[8][4];
#pragma unroll
    for (int i = 0; i < 8; i++)
#pragma unroll
        for (int j = 0; j < 4; j++) acc[i][j] = 0ull;

    const float* Xr = X + (size_t)(m0 + arow) * ldx + akq;

    {
        float4 xv = make_float4(0.f, 0.f, 0.f, 0.f);
        if (akq + 3 < C) {
            xv = *(const float4*)Xr;
        } else {
            if (akq + 0 < C) xv.x = Xr[0];
            if (akq + 1 < C) xv.y = Xr[1];
            if (akq + 2 < C) xv.z = Xr[2];
        }
        *(float2*)&As2[0][akq + 0][2 * arow] = make_float2(xv.x, xv.x);
        *(float2*)&As2[0][akq + 1][2 * arow] = make_float2(xv.y, xv.y);
        *(float2*)&As2[0][akq + 2][2 * arow] = make_float2(xv.z, xv.z);
        *(float2*)&As2[0][akq + 3][2 * arow] = make_float2(xv.w, xv.w);
        float4 wv = make_float4(0.f, 0.f, 0.f, 0.f);
        if (bk < C) wv = *(const float4*)&g_wta[(size_t)bk * Nw + n0 + bn4];
        *(float4*)&Bs[0][bk][bn4] = wv;
    }
    __syncthreads();

    int buf = 0;
    for (int c0 = 0; c0 < C; c0 += 8) {
        bool has = (c0 + 8) < C;
        float4 nxv, nwv;
        if (has) {
            nxv = *(const float4*)(Xr + c0 + 8);
            nwv = *(const float4*)&g_wta[(size_t)(c0 + 8 + bk) * Nw + n0 + bn4];
        }
#pragma unroll
        for (int k = 0; k < 8; k++) {
            ulonglong2 a01 = *(const ulonglong2*)&As2[buf][k][ty * 8];
            ulonglong2 a23 = *(const ulonglong2*)&As2[buf][k][ty * 8 + 4];
            ulonglong2 a45 = *(const ulonglong2*)&As2[buf][k][128 + ty * 8];
            ulonglong2 a67 = *(const ulonglong2*)&As2[buf][k][128 + ty * 8 + 4];
            ulonglong2 b01 = *(const ulonglong2*)&Bs[buf][k][tx * 4];
            ulonglong2 b23 = *(const ulonglong2*)&Bs[buf][k][64 + tx * 4];
            ull ar[8] = {a01.x, a01.y, a23.x, a23.y, a45.x, a45.y, a67.x, a67.y};
            ull br[4] = {b01.x, b01.y, b23.x, b23.y};
#pragma unroll
            for (int i = 0; i < 8; i++)
#pragma unroll
                for (int j = 0; j < 4; j++) acc[i][j] = ffma2(ar[i], br[j], acc[i][j]);
        }
        if (has) {
            *(float2*)&As2[buf ^ 1][akq + 0][2 * arow] = make_float2(nxv.x, nxv.x);
            *(float2*)&As2[buf ^ 1][akq + 1][2 * arow] = make_float2(nxv.y, nxv.y);
            *(float2*)&As2[buf ^ 1][akq + 2][2 * arow] = make_float2(nxv.z, nxv.z);
            *(float2*)&As2[buf ^ 1][akq + 3][2 * arow] = make_float2(nxv.w, nxv.w);
            *(float4*)&Bs[buf ^ 1][bk][bn4] = nwv;
        }
        __syncthreads();
        buf ^= 1;
    }
#pragma unroll
    for (int i = 0; i < 8; i++) {
        int m = m0 + (i >> 2) * 64 + ty * 4 + (i & 3);
        float* dst = g_ad + (size_t)m * Nw + n0;
        float4 lo, hi;
        unpack2(acc[i][0], lo.x, lo.y);
        unpack2(acc[i][1], lo.z, lo.w);
        unpack2(acc[i][2], hi.x, hi.y);
        unpack2(acc[i][3], hi.z, hi.w);
        *(float4*)&dst[tx * 4]      = lo;
        *(float4*)&dst[64 + tx * 4] = hi;
    }
}

// ---------------- gather + per-(b,n) max/min over k + partial channel sums ----------------
__global__ void k_gather(int O, int Ow) {
    int r = blockIdx.x;
    int b = r >> 10;
    __shared__ int sidx[KK];
    if (threadIdx.x < KK) sidx[threadIdx.x] = g_idx[r * KK + threadIdx.x];
    __syncthreads();
    int o = threadIdx.x;
    float dv = g_ad[(size_t)r * Ow + O + o];
    float ymx = -FLT_MAX, ymn = FLT_MAX, s1 = 0.f, s2 = 0.f;
#pragma unroll
    for (int k = 0; k < KK; k++) {
        float y = g_ad[(size_t)(b * NN + sidx[k]) * Ow + o] + dv;
        ymx = fmaxf(ymx, y);
        ymn = fminf(ymn, y);
        s1 += y;
        s2 += y * y;
    }
    g_ymax[(size_t)r * O + o] = ymx;
    g_ymin[(size_t)r * O + o] = ymn;
    g_ps1[(size_t)r * O + o] = s1;
    g_ps2[(size_t)r * O + o] = s2;
}

// ---------------- deterministic channel-stat reduction (2 levels) ----------------
__global__ void k_stat1(int O) {
    int ox = threadIdx.x & 31;
    int wy = threadIdx.x >> 5;
    int o = blockIdx.x * 32 + ox;
    int ci = blockIdx.y;
    const int CH = BN / 16;
    float s1 = 0.f, s2 = 0.f;
    int r0 = ci * CH;
    for (int r = r0 + wy; r < r0 + CH; r += 8) {
        s1 += g_ps1[(size_t)r * O + o];
        s2 += g_ps2[(size_t)r * O + o];
    }
    __shared__ float sh1[8][32], sh2[8][32];
    sh1[wy][ox] = s1; sh2[wy][ox] = s2;
    __syncthreads();
    if (wy == 0) {
        for (int w = 1; w < 8; w++) { s1 += sh1[w][ox]; s2 += sh2[w][ox]; }
        g_cs1[ci * O + o] = s1;
        g_cs2[ci * O + o] = s2;
    }
}

__global__ void k_stat2(int O, const float* __restrict__ g, const float* __restrict__ be, float invcnt) {
    int o = blockIdx.x * 256 + threadIdx.x;
    if (o >= O) return;
    float s1 = 0.f, s2 = 0.f;
    for (int ci = 0; ci < 16; ci++) { s1 += g_cs1[ci * O + o]; s2 += g_cs2[ci * O + o]; }
    float m = s1 * invcnt;
    float v = s2 * invcnt - m * m;
    float sc = g[o] * rsqrtf(v + EPSV);
    g_stats[o * 3 + 0] = m;
    g_stats[o * 3 + 1] = sc;
    g_stats[o * 3 + 2] = be[o];
}

// ---------------- finalize a block: pick max/min by sign(scale), BN affine, lrelu ----------------
__global__ void k_final(int O, int coff) {
    int r = blockIdx.x;
    int o = threadIdx.x;
    float m = g_stats[o * 3 + 0];
    float sc = g_stats[o * 3 + 1];
    float be = g_stats[o * 3 + 2];
    float y = (sc >= 0.f) ? g_ymax[(size_t)r * O + o] : g_ymin[(size_t)r * O + o];
    float t = (y - m) * sc + be;
    g_cat[(size_t)r * 512 + coff + o] = (t >= 0.f) ? t : 0.2f * t;
}

// ---------------- final stage: per-(b,o) max/min over N + channel sums ----------------
__global__ void k_fred() {
    int ox = threadIdx.x & 31;
    int wy = threadIdx.x >> 5;
    int o = blockIdx.x * 32 + ox;
    int b = blockIdx.y;
    float mx = -FLT_MAX, mn = FLT_MAX, s1 = 0.f, s2 = 0.f;
    for (int n = wy; n < NN; n += 8) {
        float v = g_ad[(size_t)(b * NN + n) * 512 + o];
        mx = fmaxf(mx, v);
        mn = fminf(mn, v);
        s1 += v;
        s2 += v * v;
    }
    __shared__ float smx[8][32], smn[8][32], ss1[8][32], ss2[8][32];
    smx[wy][ox] = mx; smn[wy][ox] = mn; ss1[wy][ox] = s1; ss2[wy][ox] = s2;
    __syncthreads();
    if (wy == 0) {
        for (int w = 1; w < 8; w++) {
            mx = fmaxf(mx, smx[w][ox]);
            mn = fminf(mn, smn[w][ox]);
            s1 += ss1[w][ox];
            s2 += ss2[w][ox];
        }
        g_bmax[b * 512 + o] = mx;
        g_bmin[b * 512 + o] = mn;
        g_bs1[b * 512 + o] = s1;
        g_bs2[b * 512 + o] = s2;
    }
}

__global__ void k_feat(const float* __restrict__ g5, const float* __restrict__ b5) {
    int o = blockIdx.x * 256 + threadIdx.x;
    if (o >= 512) return;
    float s1 = 0.f, s2 = 0.f;
    for (int b = 0; b < BB; b++) { s1 += g_bs1[b * 512 + o]; s2 += g_bs2[b * 512 + o]; }
    float m = s1 / 8192.f;
    float v = s2 / 8192.f - m * m;
    float sc = g5[o] * rsqrtf(v + EPSV);
    float be = b5[o];
    for (int b = 0; b < BB; b++) {
        float y = (sc >= 0.f) ? g_bmax[b * 512 + o] : g_bmin[b * 512 + o];
        float t = (y - m) * sc + be;
        g_feat[b * 512 + o] = (t >= 0.f) ? t : 0.2f * t;
    }
}

__global__ void k_out(const float* __restrict__ wemb, float* __restrict__ out) {
    int b = blockIdx.x;
    int f = threadIdx.x;  // 256
    __shared__ float fr[512];
    for (int i = threadIdx.x; i < 512; i += 256) fr[i] = g_feat[b * 512 + i];
    __syncthreads();
    float acc = 0.f;
    for (int o = 0; o < 512; o++) acc += fr[o] * wemb[f * 512 + o];
    out[b * 256 + f] = acc;
}

// ---------------- host orchestration ----------------
static void run_stage(const float* xext, int ldx, int coff, int C, int O,
                      const float* w, const float* g, const float* bb, int outcoff) {
    int Nw = 2 * O;
    int nW = (C * O + 255) / 256;
    int nX = (BB * C * NN) / 256;
    int nS = BN / 256;
    k_prep<<<nW + nX + nS, 256>>>(w, C, O, xext, ldx, coff, nW, nX);
    k_pair<<<dim3(36, 1, BB), 256>>>(C);
    k_gemm<<<dim3(Nw / 128, BN / 128), 256>>>(xext, ldx, coff, C, Nw);
    k_topk<<<BN / 8, 256>>>();
    k_gather<<<BN, O>>>(O, Nw);
    k_stat1<<<dim3(O / 32, 16), 256>>>(O);
    k_stat2<<<(O + 255) / 256, 256>>>(O, g, bb, 1.0f / (float)(BN * KK));
    k_final<<<BN, O>>>(O, outcoff);
}

extern "C" void kernel_launch(void* const* d_in, const int* in_sizes, int n_in,
                              void* d_out, int out_size) {
    const float* x    = (const float*)d_in[0];
    const float* w1   = (const float*)d_in[1];
    const float* g1   = (const float*)d_in[2];
    const float* b1   = (const float*)d_in[3];
    const float* w2   = (const float*)d_in[4];
    const float* g2   = (const float*)d_in[5];
    const float* b2   = (const float*)d_in[6];
    const float* w3   = (const float*)d_in[7];
    const float* g3   = (const float*)d_in[8];
    const float* b3   = (const float*)d_in[9];
    const float* w4   = (const float*)d_in[10];
    const float* g4   = (const float*)d_in[11];
    const float* b4   = (const float*)d_in[12];
    const float* w5   = (const float*)d_in[13];
    const float* g5   = (const float*)d_in[14];
    const float* b5   = (const float*)d_in[15];
    const float* wemb = (const float*)d_in[16];
    float* out = (float*)d_out;

    // edge blocks: input (ptr, ld, coff, C) -> output channels at outcoff in g_cat
    run_stage(x,       3,   0,   3,   64, w1, g1, b1,   0);
    run_stage(nullptr, 512, 0,   64,  64, w2, g2, b2,  64);
    run_stage(nullptr, 512, 64,  64, 128, w3, g3, b3, 128);
    run_stage(nullptr, 512, 128, 128, 256, w4, g4, b4, 256);

    // final: y5 = cat @ w5^T  (512x512), stats over (b,n), per-b max over n, lrelu, @ wemb^T
    k_prep_w<<<(512 * 512 + 255) / 256, 256>>>(w5, 512, 512);
    k_gemm<<<dim3(512 / 128, BN / 128), 256>>>(nullptr, 512, 0, 512, 512);
    k_fred<<<dim3(512 / 32, BB), 256>>>();
    k_feat<<<2, 256>>>(g5, b5);
    k_out<<<BB, 256>>>(wemb, out);
}

// round 14
// speedup vs baseline: 1.4668x; 1.0015x over previous
#include <cuda_runtime.h>
#include <cstdint>
#include <cfloat>

#define BB 8
#define NN 1024
#define KK 20
#define BN (BB*NN)
#define EPSV 1e-5f

typedef unsigned long long ull;

__device__ __forceinline__ void unpack2(ull v, float& lo, float& hi) {
    asm("mov.b64 {%0,%1}, %2;" : "=f"(lo), "=f"(hi) : "l"(v));
}
__device__ __forceinline__ ull ffma2(ull a, ull b, ull c) {
    ull d; asm("fma.rn.f32x2 %0, %1, %2, %3;" : "=l"(d) : "l"(a), "l"(b), "l"(c)); return d;
}

// ---------------- scratch (device globals; no runtime allocation) ----------------
__device__ float g_pair[(size_t)BB*NN*NN];   // 32MB pairwise affinities
__device__ float g_xt[BB*128*NN];            // transposed features (B, C, N), C<=128
__device__ float g_sq[BN];
__device__ int   g_idx[BN*KK];
__device__ float g_ad[BN*512];               // [a | d] per point, width Nw (<=512)
__device__ float g_ymax[BN*256];
__device__ float g_ymin[BN*256];
__device__ float g_ps1[BN*256];              // per-(b,n) partial sum of y over k
__device__ float g_ps2[BN*256];              // per-(b,n) partial sum of y^2 over k
__device__ float g_cat[BN*512];              // concatenated block outputs (B, N, 512)
__device__ float g_wta[512*512];             // [W1 | (W2-W1)]^T : (C x Nw)
__device__ float g_cs1[16*512];
__device__ float g_cs2[16*512];
__device__ float g_stats[512*3];             // mean, scale(=g*rsqrt(v+eps)), beta
__device__ float g_bmax[BB*512];
__device__ float g_bmin[BB*512];
__device__ float g_bs1[BB*512];
__device__ float g_bs2[BB*512];
__device__ float g_feat[BB*512];

__device__ __forceinline__ const float* src_ptr(const float* ext, int coff) {
    return ext ? ext : (g_cat + coff);
}

// ---------------- fused per-stage prep: weight transpose + feature transpose + sq norms ----------------
__global__ void k_prep(const float* __restrict__ w, int C, int O,
                       const float* ext, int ldx, int coff, int nW, int nX) {
    int bid = blockIdx.x;
    int tid = threadIdx.x;
    if (bid < nW) {
        int i = bid * 256 + tid;
        if (i < C * O) {
            int c = i / O, o = i % O;
            int Nw = 2 * O;
            float a = w[o * 2 * C + c];
            g_wta[c * Nw + o] = a;
            g_wta[c * Nw + O + o] = w[o * 2 * C + C + c] - a;
        }
    } else if (bid < nW + nX) {
        int i = (bid - nW) * 256 + tid;
        int n = i % NN;
        int c = (i / NN) % C;
        int b = i / (NN * C);
        const float* src = src_ptr(ext, coff);
        g_xt[(b * C + c) * NN + n] = src[(size_t)(b * NN + n) * ldx + c];
    } else {
        int r = (bid - nW - nX) * 256 + tid;
        const float* src = src_ptr(ext, coff) + (size_t)r * ldx;
        float s = 0.f;
        for (int c = 0; c < C; c++) { float v = src[c]; s += v * v; }
        g_sq[r] = s;
    }
}

// ---------------- weight transpose only (final stage) ----------------
__global__ void k_prep_w(const float* __restrict__ w, int C, int O) {
    int i = blockIdx.x * 256 + threadIdx.x;
    if (i >= C * O) return;
    int c = i / O, o = i % O;
    g_wta[c * O + o] = w[o * C + c];
}

// ---------------- pairwise affinity, 128x128 tiles, 8x8/thread, symmetric, f32x2 ----------------
// A-side (n rows) duplicated in smem so LDS yields (a,a) pairs directly.
__global__ __launch_bounds__(256) void k_pair(int C) {
    __shared__ __align__(16) float As2[2][8][264];  // duplicated n-side
    __shared__ __align__(16) float Bs[2][8][132];
    int b = blockIdx.z;
    int t = blockIdx.x;                       // triangular tile id in [0,36)
    int tn = 0;
    while (t >= 8 - tn) { t -= 8 - tn; tn++; }
    int tm = tn + t;
    int n0 = tn * 128, m0 = tm * 128;
    const float* xt = g_xt + (size_t)b * C * NN;
    int tid = threadIdx.x;
    int tx = tid & 15, ty = tid >> 4;
    int lk = tid >> 5, ln = tid & 31;

    ull acc[8][4];
#pragma unroll
    for (int i = 0; i < 8; i++)
#pragma unroll
        for (int j = 0; j < 4; j++) acc[i][j] = 0ull;

    {
        float4 va = make_float4(0.f, 0.f, 0.f, 0.f), vb = va;
        if (lk < C) {
            va = *(const float4*)&xt[lk * NN + n0 + ln * 4];
            vb = *(const float4*)&xt[lk * NN + m0 + ln * 4];
        }
        *(float4*)&As2[0][lk][ln * 8]     = make_float4(va.x, va.x, va.y, va.y);
        *(float4*)&As2[0][lk][ln * 8 + 4] = make_float4(va.z, va.z, va.w, va.w);
        *(float4*)&Bs[0][lk][ln * 4] = vb;
    }
    __syncthreads();

    int buf = 0;
    for (int c0 = 0; c0 < C; c0 += 8) {
        bool has = (c0 + 8) < C;
        float4 nva, nvb;
        if (has) {
            nva = *(const float4*)&xt[(c0 + 8 + lk) * NN + n0 + ln * 4];
            nvb = *(const float4*)&xt[(c0 + 8 + lk) * NN + m0 + ln * 4];
        }
#pragma unroll
        for (int k = 0; k < 8; k++) {
            ulonglong2 a01 = *(const ulonglong2*)&As2[buf][k][ty * 8];
            ulonglong2 a23 = *(const ulonglong2*)&As2[buf][k][ty * 8 + 4];
            ulonglong2 a45 = *(const ulonglong2*)&As2[buf][k][128 + ty * 8];
            ulonglong2 a67 = *(const ulonglong2*)&As2[buf][k][128 + ty * 8 + 4];
            ulonglong2 b01 = *(const ulonglong2*)&Bs[buf][k][tx * 4];
            ulonglong2 b23 = *(const ulonglong2*)&Bs[buf][k][64 + tx * 4];
            ull ar[8] = {a01.x, a01.y, a23.x, a23.y, a45.x, a45.y, a67.x, a67.y};
            ull br[4] = {b01.x, b01.y, b23.x, b23.y};
#pragma unroll
            for (int i = 0; i < 8; i++)
#pragma unroll
                for (int j = 0; j < 4; j++) acc[i][j] = ffma2(ar[i], br[j], acc[i][j]);
        }
        if (has) {
            *(float4*)&As2[buf ^ 1][lk][ln * 8]     = make_float4(nva.x, nva.x, nva.y, nva.y);
            *(float4*)&As2[buf ^ 1][lk][ln * 8 + 4] = make_float4(nva.z, nva.z, nva.w, nva.w);
            *(float4*)&Bs[buf ^ 1][lk][ln * 4] = nvb;
        }
        __syncthreads();
        buf ^= 1;
    }

    float sqn[8], sqm[8];
#pragma unroll
    for (int i = 0; i < 8; i++) {
        sqn[i] = g_sq[b * NN + n0 + (i >> 2) * 64 + ty * 4 + (i & 3)];
        sqm[i] = g_sq[b * NN + m0 + (i >> 2) * 64 + tx * 4 + (i & 3)];
    }
    float vals[8][8];
#pragma unroll
    for (int i = 0; i < 8; i++) {
#pragma unroll
        for (int j = 0; j < 4; j++)
            unpack2(acc[i][j], vals[i][j * 2], vals[i][j * 2 + 1]);
#pragma unroll
        for (int c = 0; c < 8; c++)
            vals[i][c] = 2.f * vals[i][c] - sqn[i] - sqm[c];
    }

    float* base = g_pair + (size_t)b * NN * NN;
#pragma unroll
    for (int i = 0; i < 8; i++) {
        int n = n0 + (i >> 2) * 64 + ty * 4 + (i & 3);
        float* dst = base + (size_t)n * NN + m0;
        *(float4*)&dst[tx * 4]      = make_float4(vals[i][0], vals[i][1], vals[i][2], vals[i][3]);
        *(float4*)&dst[64 + tx * 4] = make_float4(vals[i][4], vals[i][5], vals[i][6], vals[i][7]);
    }
    if (tn != tm) {
#pragma unroll
        for (int j = 0; j < 8; j++) {
            int m = m0 + (j >> 2) * 64 + tx * 4 + (j & 3);
            float* dst = base + (size_t)m * NN + n0;
            *(float4*)&dst[ty * 4]      = make_float4(vals[0][j], vals[1][j], vals[2][j], vals[3][j]);
            *(float4*)&dst[64 + ty * 4] = make_float4(vals[4][j], vals[5][j], vals[6][j], vals[7][j]);
        }
    }
}

// ---------------- top-K: warp per row, register tournament with group-cached argmax ----------------
// 4 groups of 8 regs per lane; winner-lane recompute touches one group only.
// Tie-break: lower global index at equal value (matches jax.lax.top_k set).
__global__ __launch_bounds__(256) void k_topk() {
    int warp = threadIdx.x >> 5, lane = threadIdx.x & 31;
    int r = blockIdx.x * 8 + warp;
    int b = r >> 10, n = r & 1023;
    const float4* row4 = (const float4*)(g_pair + (size_t)b * NN * NN + (size_t)n * NN);

    float v[32];
#pragma unroll
    for (int q = 0; q < 8; q++) {
        float4 t4 = row4[q * 32 + lane];
        v[q * 4 + 0] = t4.x;
        v[q * 4 + 1] = t4.y;
        v[q * 4 + 2] = t4.z;
        v[q * 4 + 3] = t4.w;
    }

    // group (max, argmax); strict > keeps lowest local index => lowest global idx
    float gm[4]; int gi[4];
#pragma unroll
    for (int g = 0; g < 4; g++) {
        float m = v[g * 8]; int ix = g * 8;
#pragma unroll
        for (int e = 1; e < 8; e++) {
            bool p = v[g * 8 + e] > m;
            m = p ? v[g * 8 + e] : m;
            ix = p ? g * 8 + e : ix;
        }
        gm[g] = m; gi[g] = ix;
    }
    float bm = gm[0]; int bi = gi[0];
#pragma unroll
    for (int g = 1; g < 4; g++) {
        bool p = gm[g] > bm;
        bm = p ? gm[g] : bm;
        bi = p ? gi[g] : bi;
    }

    for (int t = 0; t < KK; t++) {
        int gidx = (bi >> 2) * 128 + lane * 4 + (bi & 3);
        float wv = bm;
        int wi = gidx;
#pragma unroll
        for (int off = 16; off; off >>= 1) {
            float ov = __shfl_xor_sync(0xffffffffu, wv, off);
            int   oi = __shfl_xor_sync(0xffffffffu, wi, off);
            if (ov > wv || (ov == wv && oi < wi)) { wv = ov; wi = oi; }
        }
        if (lane == 0) g_idx[r * KK + t] = wi;
        if (wi == gidx) {                    // this lane won (gidx unique across lanes)
            int g = bi >> 3;
#pragma unroll
            for (int gg = 0; gg < 4; gg++) {
                if (g == gg) {
#pragma unroll
                    for (int e = 0; e < 8; e++)
                        v[gg * 8 + e] = (gg * 8 + e == bi) ? -FLT_MAX : v[gg * 8 + e];
                    float m = v[gg * 8]; int ix = gg * 8;
#pragma unroll
                    for (int e = 1; e < 8; e++) {
                        bool p = v[gg * 8 + e] > m;
                        m = p ? v[gg * 8 + e] : m;
                        ix = p ? gg * 8 + e : ix;
                    }
                    gm[gg] = m; gi[gg] = ix;
                }
            }
            bm = gm[0]; bi = gi[0];
#pragma unroll
            for (int g2 = 1; g2 < 4; g2++) {
                bool p = gm[g2] > bm;
                bm = p ? gm[g2] : bm;
                bi = p ? gi[g2] : bi;
            }
        }
    }
}

// ---------------- SGEMM 128x128x8, 8x8/thread, double-buffered, f32x2: g_ad = X @ g_wta ----------------
__global__ __launch_bounds__(256) void k_gemm(const float* ext, int ldx, int coff, int C, int Nw) {
    __shared__ __align__(16) float As2[2][8][264];  // duplicated A: As2[k][2m+{0,1}] = A[m]
    __shared__ __align__(16) float Bs[2][8][132];   // Bs[k][n]
    const float* X = src_ptr(ext, coff);
    int n0 = blockIdx.x * 128;
    int m0 = blockIdx.y * 128;
    int tid = threadIdx.x;
    int tx = tid & 15, ty = tid >> 4;
    int arow = tid >> 1, akq = (tid & 1) * 4;
    int bk = tid >> 5, bn4 = (tid & 31) * 4;

    ull acc[8][4];
#pragma unroll
    for (int i = 0; i < 8; i++)
#pragma unroll
        for (int j = 0; j < 4; j++) acc[i][j] = 0ull;

    const float* Xr = X + (size_t)(m0 + arow) * ldx + akq;

    {
        float4 xv = make_float4(0.f, 0.f, 0.f, 0.f);
        if (akq + 3 < C) {
            xv = *(const float4*)Xr;
        } else {
            if (akq + 0 < C) xv.x = Xr[0];
            if (akq + 1 < C) xv.y = Xr[1];
            if (akq + 2 < C) xv.z = Xr[2];
        }
        *(float2*)&As2[0][akq + 0][2 * arow] = make_float2(xv.x, xv.x);
        *(float2*)&As2[0][akq + 1][2 * arow] = make_float2(xv.y, xv.y);
        *(float2*)&As2[0][akq + 2][2 * arow] = make_float2(xv.z, xv.z);
        *(float2*)&As2[0][akq + 3][2 * arow] = make_float2(xv.w, xv.w);
        float4 wv = make_float4(0.f, 0.f, 0.f, 0.f);
        if (bk < C) wv = *(const float4*)&g_wta[(size_t)bk * Nw + n0 + bn4];
        *(float4*)&Bs[0][bk][bn4] = wv;
    }
    __syncthreads();

    int buf = 0;
    for (int c0 = 0; c0 < C; c0 += 8) {
        bool has = (c0 + 8) < C;
        float4 nxv, nwv;
        if (has) {
            nxv = *(const float4*)(Xr + c0 + 8);
            nwv = *(const float4*)&g_wta[(size_t)(c0 + 8 + bk) * Nw + n0 + bn4];
        }
#pragma unroll
        for (int k = 0; k < 8; k++) {
            ulonglong2 a01 = *(const ulonglong2*)&As2[buf][k][ty * 8];
            ulonglong2 a23 = *(const ulonglong2*)&As2[buf][k][ty * 8 + 4];
            ulonglong2 a45 = *(const ulonglong2*)&As2[buf][k][128 + ty * 8];
            ulonglong2 a67 = *(const ulonglong2*)&As2[buf][k][128 + ty * 8 + 4];
            ulonglong2 b01 = *(const ulonglong2*)&Bs[buf][k][tx * 4];
            ulonglong2 b23 = *(const ulonglong2*)&Bs[buf][k][64 + tx * 4];
            ull ar[8] = {a01.x, a01.y, a23.x, a23.y, a45.x, a45.y, a67.x, a67.y};
            ull br[4] = {b01.x, b01.y, b23.x, b23.y};
#pragma unroll
            for (int i = 0; i < 8; i++)
#pragma unroll
                for (int j = 0; j < 4; j++) acc[i][j] = ffma2(ar[i], br[j], acc[i][j]);
        }
        if (has) {
            *(float2*)&As2[buf ^ 1][akq + 0][2 * arow] = make_float2(nxv.x, nxv.x);
            *(float2*)&As2[buf ^ 1][akq + 1][2 * arow] = make_float2(nxv.y, nxv.y);
            *(float2*)&As2[buf ^ 1][akq + 2][2 * arow] = make_float2(nxv.z, nxv.z);
            *(float2*)&As2[buf ^ 1][akq + 3][2 * arow] = make_float2(nxv.w, nxv.w);
            *(float4*)&Bs[buf ^ 1][bk][bn4] = nwv;
        }
        __syncthreads();
        buf ^= 1;
    }
#pragma unroll
    for (int i = 0; i < 8; i++) {
        int m = m0 + (i >> 2) * 64 + ty * 4 + (i & 3);
        float* dst = g_ad + (size_t)m * Nw + n0;
        float4 lo, hi;
        unpack2(acc[i][0], lo.x, lo.y);
        unpack2(acc[i][1], lo.z, lo.w);
        unpack2(acc[i][2], hi.x, hi.y);
        unpack2(acc[i][3], hi.z, hi.w);
        *(float4*)&dst[tx * 4]      = lo;
        *(float4*)&dst[64 + tx * 4] = hi;
    }
}

// ---------------- gather + per-(b,n) max/min over k + partial channel sums ----------------
__global__ void k_gather(int O, int Ow) {
    int r = blockIdx.x;
    int b = r >> 10;
    __shared__ int sidx[KK];
    if (threadIdx.x < KK) sidx[threadIdx.x] = g_idx[r * KK + threadIdx.x];
    __syncthreads();
    int o = threadIdx.x;
    float dv = g_ad[(size_t)r * Ow + O + o];
    float ymx = -FLT_MAX, ymn = FLT_MAX, s1 = 0.f, s2 = 0.f;
#pragma unroll
    for (int k = 0; k < KK; k++) {
        float y = g_ad[(size_t)(b * NN + sidx[k]) * Ow + o] + dv;
        ymx = fmaxf(ymx, y);
        ymn = fminf(ymn, y);
        s1 += y;
        s2 += y * y;
    }
    g_ymax[(size_t)r * O + o] = ymx;
    g_ymin[(size_t)r * O + o] = ymn;
    g_ps1[(size_t)r * O + o] = s1;
    g_ps2[(size_t)r * O + o] = s2;
}

// ---------------- deterministic channel-stat reduction (2 levels) ----------------
__global__ void k_stat1(int O) {
    int ox = threadIdx.x & 31;
    int wy = threadIdx.x >> 5;
    int o = blockIdx.x * 32 + ox;
    int ci = blockIdx.y;
    const int CH = BN / 16;
    float s1 = 0.f, s2 = 0.f;
    int r0 = ci * CH;
    for (int r = r0 + wy; r < r0 + CH; r += 8) {
        s1 += g_ps1[(size_t)r * O + o];
        s2 += g_ps2[(size_t)r * O + o];
    }
    __shared__ float sh1[8][32], sh2[8][32];
    sh1[wy][ox] = s1; sh2[wy][ox] = s2;
    __syncthreads();
    if (wy == 0) {
        for (int w = 1; w < 8; w++) { s1 += sh1[w][ox]; s2 += sh2[w][ox]; }
        g_cs1[ci * O + o] = s1;
        g_cs2[ci * O + o] = s2;
    }
}

__global__ void k_stat2(int O, const float* __restrict__ g, const float* __restrict__ be, float invcnt) {
    int o = blockIdx.x * 256 + threadIdx.x;
    if (o >= O) return;
    float s1 = 0.f, s2 = 0.f;
    for (int ci = 0; ci < 16; ci++) { s1 += g_cs1[ci * O + o]; s2 += g_cs2[ci * O + o]; }
    float m = s1 * invcnt;
    float v = s2 * invcnt - m * m;
    float sc = g[o] * rsqrtf(v + EPSV);
    g_stats[o * 3 + 0] = m;
    g_stats[o * 3 + 1] = sc;
    g_stats[o * 3 + 2] = be[o];
}

// ---------------- finalize a block: pick max/min by sign(scale), BN affine, lrelu ----------------
__global__ void k_final(int O, int coff) {
    int r = blockIdx.x;
    int o = threadIdx.x;
    float m = g_stats[o * 3 + 0];
    float sc = g_stats[o * 3 + 1];
    float be = g_stats[o * 3 + 2];
    float y = (sc >= 0.f) ? g_ymax[(size_t)r * O + o] : g_ymin[(size_t)r * O + o];
    float t = (y - m) * sc + be;
    g_cat[(size_t)r * 512 + coff + o] = (t >= 0.f) ? t : 0.2f * t;
}

// ---------------- final stage: per-(b,o) max/min over N + channel sums ----------------
__global__ void k_fred() {
    int ox = threadIdx.x & 31;
    int wy = threadIdx.x >> 5;
    int o = blockIdx.x * 32 + ox;
    int b = blockIdx.y;
    float mx = -FLT_MAX, mn = FLT_MAX, s1 = 0.f, s2 = 0.f;
    for (int n = wy; n < NN; n += 8) {
        float v = g_ad[(size_t)(b * NN + n) * 512 + o];
        mx = fmaxf(mx, v);
        mn = fminf(mn, v);
        s1 += v;
        s2 += v * v;
    }
    __shared__ float smx[8][32], smn[8][32], ss1[8][32], ss2[8][32];
    smx[wy][ox] = mx; smn[wy][ox] = mn; ss1[wy][ox] = s1; ss2[wy][ox] = s2;
    __syncthreads();
    if (wy == 0) {
        for (int w = 1; w < 8; w++) {
            mx = fmaxf(mx, smx[w][ox]);
            mn = fminf(mn, smn[w][ox]);
            s1 += ss1[w][ox];
            s2 += ss2[w][ox];
        }
        g_bmax[b * 512 + o] = mx;
        g_bmin[b * 512 + o] = mn;
        g_bs1[b * 512 + o] = s1;
        g_bs2[b * 512 + o] = s2;
    }
}

__global__ void k_feat(const float* __restrict__ g5, const float* __restrict__ b5) {
    int o = blockIdx.x * 256 + threadIdx.x;
    if (o >= 512) return;
    float s1 = 0.f, s2 = 0.f;
    for (int b = 0; b < BB; b++) { s1 += g_bs1[b * 512 + o]; s2 += g_bs2[b * 512 + o]; }
    float m = s1 / 8192.f;
    float v = s2 / 8192.f - m * m;
    float sc = g5[o] * rsqrtf(v + EPSV);
    float be = b5[o];
    for (int b = 0; b < BB; b++) {
        float y = (sc >= 0.f) ? g_bmax[b * 512 + o] : g_bmin[b * 512 + o];
        float t = (y - m) * sc + be;
        g_feat[b * 512 + o] = (t >= 0.f) ? t : 0.2f * t;
    }
}

__global__ void k_out(const float* __restrict__ wemb, float* __restrict__ out) {
    int b = blockIdx.x;
    int f = threadIdx.x;  // 256
    __shared__ float fr[512];
    for (int i = threadIdx.x; i < 512; i += 256) fr[i] = g_feat[b * 512 + i];
    __syncthreads();
    float acc = 0.f;
    for (int o = 0; o < 512; o++) acc += fr[o] * wemb[f * 512 + o];
    out[b * 256 + f] = acc;
}

// ---------------- host orchestration ----------------
static void run_stage(const float* xext, int ldx, int coff, int C, int O,
                      const float* w, const float* g, const float* bb, int outcoff) {
    int Nw = 2 * O;
    int nW = (C * O + 255) / 256;
    int nX = (BB * C * NN) / 256;
    int nS = BN / 256;
    k_prep<<<nW + nX + nS, 256>>>(w, C, O, xext, ldx, coff, nW, nX);
    k_pair<<<dim3(36, 1, BB), 256>>>(C);
    k_gemm<<<dim3(Nw / 128, BN / 128), 256>>>(xext, ldx, coff, C, Nw);
    k_topk<<<BN / 8, 256>>>();
    k_gather<<<BN, O>>>(O, Nw);
    k_stat1<<<dim3(O / 32, 16), 256>>>(O);
    k_stat2<<<(O + 255) / 256, 256>>>(O, g, bb, 1.0f / (float)(BN * KK));
    k_final<<<BN, O>>>(O, outcoff);
}

extern "C" void kernel_launch(void* const* d_in, const int* in_sizes, int n_in,
                              void* d_out, int out_size) {
    const float* x    = (const float*)d_in[0];
    const float* w1   = (const float*)d_in[1];
    const float* g1   = (const float*)d_in[2];
    const float* b1   = (const float*)d_in[3];
    const float* w2   = (const float*)d_in[4];
    const float* g2   = (const float*)d_in[5];
    const float* b2   = (const float*)d_in[6];
    const float* w3   = (const float*)d_in[7];
    const float* g3   = (const float*)d_in[8];
    const float* b3   = (const float*)d_in[9];
    const float* w4   = (const float*)d_in[10];
    const float* g4   = (const float*)d_in[11];
    const float* b4   = (const float*)d_in[12];
    const float* w5   = (const float*)d_in[13];
    const float* g5   = (const float*)d_in[14];
    const float* b5   = (const float*)d_in[15];
    const float* wemb = (const float*)d_in[16];
    float* out = (float*)d_out;

    // edge blocks: input (ptr, ld, coff, C) -> output channels at outcoff in g_cat
    run_stage(x,       3,   0,   3,   64, w1, g1, b1,   0);
    run_stage(nullptr, 512, 0,   64,  64, w2, g2, b2,  64);
    run_stage(nullptr, 512, 64,  64, 128, w3, g3, b3, 128);
    run_stage(nullptr, 512, 128, 128, 256, w4, g4, b4, 256);

    // final: y5 = cat @ w5^T  (512x512), stats over (b,n), per-b max over n, lrelu, @ wemb^T
    k_prep_w<<<(512 * 512 + 255) / 256, 256>>>(w5, 512, 512);
    k_gemm<<<dim3(512 / 128, BN / 128), 256>>>(nullptr, 512, 0, 512, 512);
    k_fred<<<dim3(512 / 32, BB), 256>>>();
    k_feat<<<2, 256>>>(g5, b5);
    k_out<<<BB, 256>>>(wemb, out);
}

// round 17
// speedup vs baseline: 1.4821x; 1.0105x over previous
#include <cuda_runtime.h>
#include <cstdint>
#include <cfloat>

#define BB 8
#define NN 1024
#define KK 20
#define BN (BB*NN)
#define EPSV 1e-5f

typedef unsigned long long ull;

__device__ __forceinline__ void unpack2(ull v, float& lo, float& hi) {
    asm("mov.b64 {%0,%1}, %2;" : "=f"(lo), "=f"(hi) : "l"(v));
}
__device__ __forceinline__ ull ffma2(ull a, ull b, ull c) {
    ull d; asm("fma.rn.f32x2 %0, %1, %2, %3;" : "=l"(d) : "l"(a), "l"(b), "l"(c)); return d;
}

// ---------------- scratch (device globals; no runtime allocation) ----------------
__device__ float g_pair[(size_t)BB*NN*NN];   // 32MB pairwise affinities
__device__ float g_xt[BB*128*NN];            // transposed features (B, C, N), C<=128
__device__ float g_sq[BN];
__device__ int   g_idx[BN*KK];
__device__ float g_ad[BN*512];               // [a | d] per point, width Nw (<=512)
__device__ float g_ymax[BN*256];
__device__ float g_ymin[BN*256];
__device__ float g_ps1[BN*256];              // per-(b,n) partial sum of y over k
__device__ float g_ps2[BN*256];              // per-(b,n) partial sum of y^2 over k
__device__ float g_cat[BN*512];              // concatenated block outputs (B, N, 512)
__device__ float g_wta[512*512];             // [W1 | (W2-W1)]^T : (C x Nw)
__device__ float g_cs1[16*512];
__device__ float g_cs2[16*512];
__device__ float g_stats[512*3];             // mean, scale(=g*rsqrt(v+eps)), beta
__device__ float g_bmax[BB*512];
__device__ float g_bmin[BB*512];
__device__ float g_bs1[BB*512];
__device__ float g_bs2[BB*512];
__device__ float g_feat[BB*512];

__device__ __forceinline__ const float* src_ptr(const float* ext, int coff) {
    return ext ? ext : (g_cat + coff);
}

// ---------------- fused per-stage prep: weight transpose + feature transpose + sq norms ----------------
__global__ void k_prep(const float* __restrict__ w, int C, int O,
                       const float* ext, int ldx, int coff, int nW, int nX) {
    int bid = blockIdx.x;
    int tid = threadIdx.x;
    if (bid < nW) {
        int i = bid * 256 + tid;
        if (i < C * O) {
            int c = i / O, o = i % O;
            int Nw = 2 * O;
            float a = w[o * 2 * C + c];
            g_wta[c * Nw + o] = a;
            g_wta[c * Nw + O + o] = w[o * 2 * C + C + c] - a;
        }
    } else if (bid < nW + nX) {
        int i = (bid - nW) * 256 + tid;
        int n = i % NN;
        int c = (i / NN) % C;
        int b = i / (NN * C);
        const float* src = src_ptr(ext, coff);
        g_xt[(b * C + c) * NN + n] = src[(size_t)(b * NN + n) * ldx + c];
    } else {
        int r = (bid - nW - nX) * 256 + tid;
        const float* src = src_ptr(ext, coff) + (size_t)r * ldx;
        float s = 0.f;
        for (int c = 0; c < C; c++) { float v = src[c]; s += v * v; }
        g_sq[r] = s;
    }
}

// ---------------- weight transpose only (final stage) ----------------
__global__ void k_prep_w(const float* __restrict__ w, int C, int O) {
    int i = blockIdx.x * 256 + threadIdx.x;
    if (i >= C * O) return;
    int c = i / O, o = i % O;
    g_wta[c * O + o] = w[o * C + c];
}

// ---------------- pairwise affinity, 128x128 tiles, 8x8/thread, symmetric, f32x2 ----------------
// A-side (n rows) duplicated in smem so LDS yields (a,a) pairs directly.
__global__ __launch_bounds__(256) void k_pair(int C) {
    __shared__ __align__(16) float As2[2][8][264];  // duplicated n-side
    __shared__ __align__(16) float Bs[2][8][132];
    int b = blockIdx.z;
    int t = blockIdx.x;                       // triangular tile id in [0,36)
    int tn = 0;
    while (t >= 8 - tn) { t -= 8 - tn; tn++; }
    int tm = tn + t;
    int n0 = tn * 128, m0 = tm * 128;
    const float* xt = g_xt + (size_t)b * C * NN;
    int tid = threadIdx.x;
    int tx = tid & 15, ty = tid >> 4;
    int lk = tid >> 5, ln = tid & 31;

    ull acc[8][4];
#pragma unroll
    for (int i = 0; i < 8; i++)
#pragma unroll
        for (int j = 0; j < 4; j++) acc[i][j] = 0ull;

    {
        float4 va = make_float4(0.f, 0.f, 0.f, 0.f), vb = va;
        if (lk < C) {
            va = *(const float4*)&xt[lk * NN + n0 + ln * 4];
            vb = *(const float4*)&xt[lk * NN + m0 + ln * 4];
        }
        *(float4*)&As2[0][lk][ln * 8]     = make_float4(va.x, va.x, va.y, va.y);
        *(float4*)&As2[0][lk][ln * 8 + 4] = make_float4(va.z, va.z, va.w, va.w);
        *(float4*)&Bs[0][lk][ln * 4] = vb;
    }
    __syncthreads();

    int buf = 0;
    for (int c0 = 0; c0 < C; c0 += 8) {
        bool has = (c0 + 8) < C;
        float4 nva, nvb;
        if (has) {
            nva = *(const float4*)&xt[(c0 + 8 + lk) * NN + n0 + ln * 4];
            nvb = *(const float4*)&xt[(c0 + 8 + lk) * NN + m0 + ln * 4];
        }
#pragma unroll
        for (int k = 0; k < 8; k++) {
            ulonglong2 a01 = *(const ulonglong2*)&As2[buf][k][ty * 8];
            ulonglong2 a23 = *(const ulonglong2*)&As2[buf][k][ty * 8 + 4];
            ulonglong2 a45 = *(const ulonglong2*)&As2[buf][k][128 + ty * 8];
            ulonglong2 a67 = *(const ulonglong2*)&As2[buf][k][128 + ty * 8 + 4];
            ulonglong2 b01 = *(const ulonglong2*)&Bs[buf][k][tx * 4];
            ulonglong2 b23 = *(const ulonglong2*)&Bs[buf][k][64 + tx * 4];
            ull ar[8] = {a01.x, a01.y, a23.x, a23.y, a45.x, a45.y, a67.x, a67.y};
            ull br[4] = {b01.x, b01.y, b23.x, b23.y};
#pragma unroll
            for (int i = 0; i < 8; i++)
#pragma unroll
                for (int j = 0; j < 4; j++) acc[i][j] = ffma2(ar[i], br[j], acc[i][j]);
        }
        if (has) {
            *(float4*)&As2[buf ^ 1][lk][ln * 8]     = make_float4(nva.x, nva.x, nva.y, nva.y);
            *(float4*)&As2[buf ^ 1][lk][ln * 8 + 4] = make_float4(nva.z, nva.z, nva.w, nva.w);
            *(float4*)&Bs[buf ^ 1][lk][ln * 4] = nvb;
        }
        __syncthreads();
        buf ^= 1;
    }

    float sqn[8], sqm[8];
#pragma unroll
    for (int i = 0; i < 8; i++) {
        sqn[i] = g_sq[b * NN + n0 + (i >> 2) * 64 + ty * 4 + (i & 3)];
        sqm[i] = g_sq[b * NN + m0 + (i >> 2) * 64 + tx * 4 + (i & 3)];
    }
    float vals[8][8];
#pragma unroll
    for (int i = 0; i < 8; i++) {
#pragma unroll
        for (int j = 0; j < 4; j++)
            unpack2(acc[i][j], vals[i][j * 2], vals[i][j * 2 + 1]);
#pragma unroll
        for (int c = 0; c < 8; c++)
            vals[i][c] = 2.f * vals[i][c] - sqn[i] - sqm[c];
    }

    float* base = g_pair + (size_t)b * NN * NN;
#pragma unroll
    for (int i = 0; i < 8; i++) {
        int n = n0 + (i >> 2) * 64 + ty * 4 + (i & 3);
        float* dst = base + (size_t)n * NN + m0;
        *(float4*)&dst[tx * 4]      = make_float4(vals[i][0], vals[i][1], vals[i][2], vals[i][3]);
        *(float4*)&dst[64 + tx * 4] = make_float4(vals[i][4], vals[i][5], vals[i][6], vals[i][7]);
    }
    if (tn != tm) {
#pragma unroll
        for (int j = 0; j < 8; j++) {
            int m = m0 + (j >> 2) * 64 + tx * 4 + (j & 3);
            float* dst = base + (size_t)m * NN + n0;
            *(float4*)&dst[ty * 4]      = make_float4(vals[0][j], vals[1][j], vals[2][j], vals[3][j]);
            *(float4*)&dst[64 + ty * 4] = make_float4(vals[4][j], vals[5][j], vals[6][j], vals[7][j]);
        }
    }
}

// ---------------- top-K: warp per row, register tournament with group-cached argmax ----------------
// 4 groups of 8 regs per lane; winner-lane recompute touches one group only.
// Tie-break: lower global index at equal value (matches jax.lax.top_k set).
__global__ __launch_bounds__(256) void k_topk() {
    int warp = threadIdx.x >> 5, lane = threadIdx.x & 31;
    int r = blockIdx.x * 8 + warp;
    int b = r >> 10, n = r & 1023;
    const float4* row4 = (const float4*)(g_pair + (size_t)b * NN * NN + (size_t)n * NN);

    float v[32];
#pragma unroll
    for (int q = 0; q < 8; q++) {
        float4 t4 = row4[q * 32 + lane];
        v[q * 4 + 0] = t4.x;
        v[q * 4 + 1] = t4.y;
        v[q * 4 + 2] = t4.z;
        v[q * 4 + 3] = t4.w;
    }

    // group (max, argmax); strict > keeps lowest local index => lowest global idx
    float gm[4]; int gi[4];
#pragma unroll
    for (int g = 0; g < 4; g++) {
        float m = v[g * 8]; int ix = g * 8;
#pragma unroll
        for (int e = 1; e < 8; e++) {
            bool p = v[g * 8 + e] > m;
            m = p ? v[g * 8 + e] : m;
            ix = p ? g * 8 + e : ix;
        }
        gm[g] = m; gi[g] = ix;
    }
    float bm = gm[0]; int bi = gi[0];
#pragma unroll
    for (int g = 1; g < 4; g++) {
        bool p = gm[g] > bm;
        bm = p ? gm[g] : bm;
        bi = p ? gi[g] : bi;
    }

    for (int t = 0; t < KK; t++) {
        int gidx = (bi >> 2) * 128 + lane * 4 + (bi & 3);
        float wv = bm;
        int wi = gidx;
#pragma unroll
        for (int off = 16; off; off >>= 1) {
            float ov = __shfl_xor_sync(0xffffffffu, wv, off);
            int   oi = __shfl_xor_sync(0xffffffffu, wi, off);
            if (ov > wv || (ov == wv && oi < wi)) { wv = ov; wi = oi; }
        }
        if (lane == 0) g_idx[r * KK + t] = wi;
        if (wi == gidx) {                    // this lane won (gidx unique across lanes)
            int g = bi >> 3;
#pragma unroll
            for (int gg = 0; gg < 4; gg++) {
                if (g == gg) {
#pragma unroll
                    for (int e = 0; e < 8; e++)
                        v[gg * 8 + e] = (gg * 8 + e == bi) ? -FLT_MAX : v[gg * 8 + e];
                    float m = v[gg * 8]; int ix = gg * 8;
#pragma unroll
                    for (int e = 1; e < 8; e++) {
                        bool p = v[gg * 8 + e] > m;
                        m = p ? v[gg * 8 + e] : m;
                        ix = p ? gg * 8 + e : ix;
                    }
                    gm[gg] = m; gi[gg] = ix;
                }
            }
            bm = gm[0]; bi = gi[0];
#pragma unroll
            for (int g2 = 1; g2 < 4; g2++) {
                bool p = gm[g2] > bm;
                bm = p ? gm[g2] : bm;
                bi = p ? gi[g2] : bi;
            }
        }
    }
}

// ---------------- SGEMM 128x128x8, 8x8/thread, double-buffered, f32x2: g_ad = X @ g_wta ----------------
__global__ __launch_bounds__(256) void k_gemm(const float* ext, int ldx, int coff, int C, int Nw) {
    __shared__ __align__(16) float As2[2][8][264];  // duplicated A: As2[k][2m+{0,1}] = A[m]
    __shared__ __align__(16) float Bs[2][8][132];   // Bs[k][n]
    const float* X = src_ptr(ext, coff);
    int n0 = blockIdx.x * 128;
    int m0 = blockIdx.y * 128;
    int tid = threadIdx.x;
    int tx = tid & 15, ty = tid >> 4;
    int arow = tid >> 1, akq = (tid & 1) * 4;
    int bk = tid >> 5, bn4 = (tid & 31) * 4;

    ull acc[8][4];
#pragma unroll
    for (int i = 0; i < 8; i++)
#pragma unroll
        for (int j = 0; j < 4; j++) acc[i][j] = 0ull;

    const float* Xr = X + (size_t)(m0 + arow) * ldx + akq;

    {
        float4 xv = make_float4(0.f, 0.f, 0.f, 0.f);
        if (akq + 3 < C) {
            xv = *(const float4*)Xr;
        } else {
            if (akq + 0 < C) xv.x = Xr[0];
            if (akq + 1 < C) xv.y = Xr[1];
            if (akq + 2 < C) xv.z = Xr[2];
        }
        *(float2*)&As2[0][akq + 0][2 * arow] = make_float2(xv.x, xv.x);
        *(float2*)&As2[0][akq + 1][2 * arow] = make_float2(xv.y, xv.y);
        *(float2*)&As2[0][akq + 2][2 * arow] = make_float2(xv.z, xv.z);
        *(float2*)&As2[0][akq + 3][2 * arow] = make_float2(xv.w, xv.w);
        float4 wv = make_float4(0.f, 0.f, 0.f, 0.f);
        if (bk < C) wv = *(const float4*)&g_wta[(size_t)bk * Nw + n0 + bn4];
        *(float4*)&Bs[0][bk][bn4] = wv;
    }
    __syncthreads();

    int buf = 0;
    for (int c0 = 0; c0 < C; c0 += 8) {
        bool has = (c0 + 8) < C;
        float4 nxv, nwv;
        if (has) {
            nxv = *(const float4*)(Xr + c0 + 8);
            nwv = *(const float4*)&g_wta[(size_t)(c0 + 8 + bk) * Nw + n0 + bn4];
        }
#pragma unroll
        for (int k = 0; k < 8; k++) {
            ulonglong2 a01 = *(const ulonglong2*)&As2[buf][k][ty * 8];
            ulonglong2 a23 = *(const ulonglong2*)&As2[buf][k][ty * 8 + 4];
            ulonglong2 a45 = *(const ulonglong2*)&As2[buf][k][128 + ty * 8];
            ulonglong2 a67 = *(const ulonglong2*)&As2[buf][k][128 + ty * 8 + 4];
            ulonglong2 b01 = *(const ulonglong2*)&Bs[buf][k][tx * 4];
            ulonglong2 b23 = *(const ulonglong2*)&Bs[buf][k][64 + tx * 4];
            ull ar[8] = {a01.x, a01.y, a23.x, a23.y, a45.x, a45.y, a67.x, a67.y};
            ull br[4] = {b01.x, b01.y, b23.x, b23.y};
#pragma unroll
            for (int i = 0; i < 8; i++)
#pragma unroll
                for (int j = 0; j < 4; j++) acc[i][j] = ffma2(ar[i], br[j], acc[i][j]);
        }
        if (has) {
            *(float2*)&As2[buf ^ 1][akq + 0][2 * arow] = make_float2(nxv.x, nxv.x);
            *(float2*)&As2[buf ^ 1][akq + 1][2 * arow] = make_float2(nxv.y, nxv.y);
            *(float2*)&As2[buf ^ 1][akq + 2][2 * arow] = make_float2(nxv.z, nxv.z);
            *(float2*)&As2[buf ^ 1][akq + 3][2 * arow] = make_float2(nxv.w, nxv.w);
            *(float4*)&Bs[buf ^ 1][bk][bn4] = nwv;
        }
        __syncthreads();
        buf ^= 1;
    }
#pragma unroll
    for (int i = 0; i < 8; i++) {
        int m = m0 + (i >> 2) * 64 + ty * 4 + (i & 3);
        float* dst = g_ad + (size_t)m * Nw + n0;
        float4 lo, hi;
        unpack2(acc[i][0], lo.x, lo.y);
        unpack2(acc[i][1], lo.z, lo.w);
        unpack2(acc[i][2], hi.x, hi.y);
        unpack2(acc[i][3], hi.z, hi.w);
        *(float4*)&dst[tx * 4]      = lo;
        *(float4*)&dst[64 + tx * 4] = hi;
    }
}

// ---------------- gather + per-(b,n) max/min over k + partial channel sums ----------------
__global__ void k_gather(int O, int Ow) {
    int r = blockIdx.x;
    int b = r >> 10;
    __shared__ int sidx[KK];
    if (threadIdx.x < KK) sidx[threadIdx.x] = g_idx[r * KK + threadIdx.x];
    __syncthreads();
    int o = threadIdx.x;
    float dv = g_ad[(size_t)r * Ow + O + o];
    float ymx = -FLT_MAX, ymn = FLT_MAX, s1 = 0.f, s2 = 0.f;
#pragma unroll
    for (int k = 0; k < KK; k++) {
        float y = g_ad[(size_t)(b * NN + sidx[k]) * Ow + o] + dv;
        ymx = fmaxf(ymx, y);
        ymn = fminf(ymn, y);
        s1 += y;
        s2 += y * y;
    }
    g_ymax[(size_t)r * O + o] = ymx;
    g_ymin[(size_t)r * O + o] = ymn;
    g_ps1[(size_t)r * O + o] = s1;
    g_ps2[(size_t)r * O + o] = s2;
}

// ---------------- deterministic channel-stat reduction (2 levels) ----------------
__global__ void k_stat1(int O) {
    int ox = threadIdx.x & 31;
    int wy = threadIdx.x >> 5;
    int o = blockIdx.x * 32 + ox;
    int ci = blockIdx.y;
    const int CH = BN / 16;
    float s1 = 0.f, s2 = 0.f;
    int r0 = ci * CH;
    for (int r = r0 + wy; r < r0 + CH; r += 8) {
        s1 += g_ps1[(size_t)r * O + o];
        s2 += g_ps2[(size_t)r * O + o];
    }
    __shared__ float sh1[8][32], sh2[8][32];
    sh1[wy][ox] = s1; sh2[wy][ox] = s2;
    __syncthreads();
    if (wy == 0) {
        for (int w = 1; w < 8; w++) { s1 += sh1[w][ox]; s2 += sh2[w][ox]; }
        g_cs1[ci * O + o] = s1;
        g_cs2[ci * O + o] = s2;
    }
}

__global__ void k_stat2(int O, const float* __restrict__ g, const float* __restrict__ be, float invcnt) {
    int o = blockIdx.x * 256 + threadIdx.x;
    if (o >= O) return;
    float s1 = 0.f, s2 = 0.f;
    for (int ci = 0; ci < 16; ci++) { s1 += g_cs1[ci * O + o]; s2 += g_cs2[ci * O + o]; }
    float m = s1 * invcnt;
    float v = s2 * invcnt - m * m;
    float sc = g[o] * rsqrtf(v + EPSV);
    g_stats[o * 3 + 0] = m;
    g_stats[o * 3 + 1] = sc;
    g_stats[o * 3 + 2] = be[o];
}

// ---------------- finalize a block: pick max/min by sign(scale), BN affine, lrelu ----------------
__global__ void k_final(int O, int coff) {
    int r = blockIdx.x;
    int o = threadIdx.x;
    float m = g_stats[o * 3 + 0];
    float sc = g_stats[o * 3 + 1];
    float be = g_stats[o * 3 + 2];
    float y = (sc >= 0.f) ? g_ymax[(size_t)r * O + o] : g_ymin[(size_t)r * O + o];
    float t = (y - m) * sc + be;
    g_cat[(size_t)r * 512 + coff + o] = (t >= 0.f) ? t : 0.2f * t;
}

// ---------------- final stage: per-(b,o) max/min over N + channel sums ----------------
__global__ void k_fred() {
    int ox = threadIdx.x & 31;
    int wy = threadIdx.x >> 5;
    int o = blockIdx.x * 32 + ox;
    int b = blockIdx.y;
    float mx = -FLT_MAX, mn = FLT_MAX, s1 = 0.f, s2 = 0.f;
    for (int n = wy; n < NN; n += 8) {
        float v = g_ad[(size_t)(b * NN + n) * 512 + o];
        mx = fmaxf(mx, v);
        mn = fminf(mn, v);
        s1 += v;
        s2 += v * v;
    }
    __shared__ float smx[8][32], smn[8][32], ss1[8][32], ss2[8][32];
    smx[wy][ox] = mx; smn[wy][ox] = mn; ss1[wy][ox] = s1; ss2[wy][ox] = s2;
    __syncthreads();
    if (wy == 0) {
        for (int w = 1; w < 8; w++) {
            mx = fmaxf(mx, smx[w][ox]);
            mn = fminf(mn, smn[w][ox]);
            s1 += ss1[w][ox];
            s2 += ss2[w][ox];
        }
        g_bmax[b * 512 + o] = mx;
        g_bmin[b * 512 + o] = mn;
        g_bs1[b * 512 + o] = s1;
        g_bs2[b * 512 + o] = s2;
    }
}

__global__ void k_feat(const float* __restrict__ g5, const float* __restrict__ b5) {
    int o = blockIdx.x * 256 + threadIdx.x;
    if (o >= 512) return;
    float s1 = 0.f, s2 = 0.f;
    for (int b = 0; b < BB; b++) { s1 += g_bs1[b * 512 + o]; s2 += g_bs2[b * 512 + o]; }
    float m = s1 / 8192.f;
    float v = s2 / 8192.f - m * m;
    float sc = g5[o] * rsqrtf(v + EPSV);
    float be = b5[o];
    for (int b = 0; b < BB; b++) {
        float y = (sc >= 0.f) ? g_bmax[b * 512 + o] : g_bmin[b * 512 + o];
        float t = (y - m) * sc + be;
        g_feat[b * 512 + o] = (t >= 0.f) ? t : 0.2f * t;
    }
}

__global__ void k_out(const float* __restrict__ wemb, float* __restrict__ out) {
    int b = blockIdx.x;
    int f = threadIdx.x;  // 256
    __shared__ float fr[512];
    for (int i = threadIdx.x; i < 512; i += 256) fr[i] = g_feat[b * 512 + i];
    __syncthreads();
    float acc = 0.f;
    for (int o = 0; o < 512; o++) acc += fr[o] * wemb[f * 512 + o];
    out[b * 256 + f] = acc;
}

// ---------------- host orchestration ----------------
static void run_stage(const float* xext, int ldx, int coff, int C, int O,
                      const float* w, const float* g, const float* bb, int outcoff) {
    int Nw = 2 * O;
    int nW = (C * O + 255) / 256;
    int nX = (BB * C * NN) / 256;
    int nS = BN / 256;
    k_prep<<<nW + nX + nS, 256>>>(w, C, O, xext, ldx, coff, nW, nX);
    k_pair<<<dim3(36, 1, BB), 256>>>(C);
    k_gemm<<<dim3(Nw / 128, BN / 128), 256>>>(xext, ldx, coff, C, Nw);
    k_topk<<<BN / 8, 256>>>();
    k_gather<<<BN, O>>>(O, Nw);
    k_stat1<<<dim3(O / 32, 16), 256>>>(O);
    k_stat2<<<(O + 255) / 256, 256>>>(O, g, bb, 1.0f / (float)(BN * KK));
    k_final<<<BN, O>>>(O, outcoff);
}

extern "C" void kernel_launch(void* const* d_in, const int* in_sizes, int n_in,
                              void* d_out, int out_size) {
    const float* x    = (const float*)d_in[0];
    const float* w1   = (const float*)d_in[1];
    const float* g1   = (const float*)d_in[2];
    const float* b1   = (const float*)d_in[3];
    const float* w2   = (const float*)d_in[4];
    const float* g2   = (const float*)d_in[5];
    const float* b2   = (const float*)d_in[6];
    const float* w3   = (const float*)d_in[7];
    const float* g3   = (const float*)d_in[8];
    const float* b3   = (const float*)d_in[9];
    const float* w4   = (const float*)d_in[10];
    const float* g4   = (const float*)d_in[11];
    const float* b4   = (const float*)d_in[12];
    const float* w5   = (const float*)d_in[13];
    const float* g5   = (const float*)d_in[14];
    const float* b5   = (const float*)d_in[15];
    const float* wemb = (const float*)d_in[16];
    float* out = (float*)d_out;

    // edge blocks: input (ptr, ld, coff, C) -> output channels at outcoff in g_cat
    run_stage(x,       3,   0,   3,   64, w1, g1, b1,   0);
    run_stage(nullptr, 512, 0,   64,  64, w2, g2, b2,  64);
    run_stage(nullptr, 512, 64,  64, 128, w3, g3, b3, 128);
    run_stage(nullptr, 512, 128, 128, 256, w4, g4, b4, 256);

    // final: y5 = cat @ w5^T  (512x512), stats over (b,n), per-b max over n, lrelu, @ wemb^T
    k_prep_w<<<(512 * 512 + 255) / 256, 256>>>(w5, 512, 512);
    k_gemm<<<dim3(512 / 128, BN / 128), 256>>>(nullptr, 512, 0, 512, 512);
    k_fred<<<dim3(512 / 32, BB), 256>>>();
    k_feat<<<2, 256>>>(g5, b5);
    k_out<<<BB, 256>>>(wemb, out);
}